// round 10
// baseline (speedup 1.0000x reference)
#include <cuda_runtime.h>
#include <cuda_fp16.h>
#include <math.h>

// Problem constants: B=2, M=N=64, H=2, C=8, D=4
#define TOK  4096
#define TOT  8192

#define SCALE_LOG2E 0.72134752044448170f   // 0.5 * log2(e)
#define PP2 72                              // pos half2 row pitch (uint4-copyable)

// Scratch (allocation-free: __device__ globals)
__device__ float  g_x1[65536];
__device__ float  g_q[65536];      // [bh][t][d], pre-scaled by 0.5*log2e
__device__ float  g_k[65536];
__device__ float  g_v[65536];
__device__ float  g_a[65536];
__device__ uint4  g_kh[16384];     // [bh][t]: 4 duplicated half2 (one per d)
__device__ __half2 g_ph[2 * 128 * PP2];  // [h][128 rows][PP2]: (P[c],P[c+1]) prescaled

__device__ __forceinline__ float gelu_f(float x) {
    float z2 = 1.5957691216057308f * fmaf(0.044715f, x * x * x, x);  // 2z
    return __fdividef(x, 1.0f + __expf(-z2));
}
__device__ __forceinline__ float ex2(float x) {
    float r; asm("ex2.approx.ftz.f32 %0, %1;" : "=f"(r) : "f"(x)); return r;
}
__device__ __forceinline__ __half2 h2ex2(__half2 x) {
    __half2 r;
    asm("ex2.approx.f16x2 %0, %1;"
        : "=r"(*reinterpret_cast<unsigned*>(&r))
        : "r"(*reinterpret_cast<const unsigned*>(&x)));
    return r;
}

// ---------------- Stage 1: gelu + circular conv (8->8) + residual + QKV ----------------
// 4x8 token tile, 512 thr, 16 thr/token (cin x out-half). Also fills g_ph. grid=256.
__global__ void __launch_bounds__(512) k_conv_qkv(
        const float* __restrict__ x, const float* __restrict__ W,
        const float* __restrict__ bias, const float* __restrict__ Wq,
        const float* __restrict__ Wk, const float* __restrict__ Wv,
        const float* __restrict__ pos) {
    __shared__ float sW[576];
    __shared__ float sb[8];
    __shared__ float sQKV[192];
    __shared__ float sX[60 * 8];   // 6x10 halo gelu tile
    int tid = threadIdx.x;
    for (int i = tid; i < 576; i += 512) sW[i] = W[i];
    if (tid < 8) sb[tid] = bias[tid];
    if (tid < 64) {
        sQKV[tid]       = Wq[tid];
        sQKV[64 + tid]  = Wk[tid];
        sQKV[128 + tid] = Wv[tid];
    }

    // pos half2 table conversion (first 36 blocks cover 2*128*PP2 = 18432 entries)
    int gid = blockIdx.x * 512 + tid;
    if (gid < 2 * 128 * PP2) {
        int hh = gid / (128 * PP2);
        int rem = gid - hh * (128 * PP2);
        int r = rem / PP2, c = rem - r * PP2;
        const float* gP = pos + hh * 4096 + ((r & 63) << 6);
        g_ph[gid] = __floats2half2_rn(gP[c & 63] * SCALE_LOG2E,
                                      gP[(c + 1) & 63] * SCALE_LOG2E);
    }

    int b = blockIdx.x >> 7;
    int tile = blockIdx.x & 127;
    int ti = tile >> 3, tj = tile & 7;
    // gelu the 6x10 halo (480 channel-cells), 1 per thread
    if (tid < 480) {
        int cell = tid >> 3, ch = tid & 7;
        int pi = cell / 10, pj = cell - pi * 10;
        int row = (ti * 4 + pi - 1) & 63;
        int col = (tj * 8 + pj - 1) & 63;
        sX[tid] = gelu_f(x[((((b << 12) | (row << 6)) | col) << 3) + ch]);
    }
    __syncthreads();

    int token = tid >> 4, half = (tid >> 3) & 1, cin = tid & 7;
    int li = token >> 3, lj = token & 7;
    int p = (b << 12) | ((ti * 4 + li) << 6) | (tj * 8 + lj);
    float acc[4];
#pragma unroll
    for (int c = 0; c < 4; c++) acc[c] = 0.f;
#pragma unroll
    for (int di = 0; di < 3; di++) {
#pragma unroll
        for (int dj = 0; dj < 3; dj++) {
            float xv = sX[((li + di) * 10 + (lj + dj)) * 8 + cin];
            const float* wp = sW + (di * 3 + dj) * 64 + cin * 8 + half * 4;
#pragma unroll
            for (int c = 0; c < 4; c++) acc[c] = fmaf(xv, wp[c], acc[c]);
        }
    }
    // reduce over cin (bits 0-2 of lane)
#pragma unroll
    for (int c = 0; c < 4; c++) acc[c] += __shfl_xor_sync(0xffffffffu, acc[c], 1);
#pragma unroll
    for (int c = 0; c < 4; c++) acc[c] += __shfl_xor_sync(0xffffffffu, acc[c], 2);
#pragma unroll
    for (int c = 0; c < 4; c++) acc[c] += __shfl_xor_sync(0xffffffffu, acc[c], 4);
    // bias + residual (each thread keeps its half's 4 channels)
#pragma unroll
    for (int c = 0; c < 4; c++)
        acc[c] += sb[half * 4 + c] + x[p * 8 + half * 4 + c];
    // exchange halves -> full y[8]
    float oth[4];
#pragma unroll
    for (int c = 0; c < 4; c++) oth[c] = __shfl_xor_sync(0xffffffffu, acc[c], 8);
    float y[8];
#pragma unroll
    for (int c = 0; c < 4; c++) {
        y[half * 4 + c] = acc[c] * 0.70710678118654752f;
        y[(1 - half) * 4 + c] = oth[c] * 0.70710678118654752f;
    }

    int t = p & 4095;
    int kind = cin >> 1;            // 0=x1, 1=q, 2=k, 3=v
    int e0 = half * 4 + (cin & 1) * 2;
    if (kind == 0) {
        *(float2*)(g_x1 + p * 8 + e0) =
            make_float2(acc[(cin & 1) * 2], acc[(cin & 1) * 2 + 1]);
    } else {
        const float* wsel = sQKV + (kind - 1) * 64;
        float v0 = 0.f, v1 = 0.f;
#pragma unroll
        for (int c = 0; c < 8; c++) {
            v0 = fmaf(y[c], wsel[c * 8 + e0], v0);
            v1 = fmaf(y[c], wsel[c * 8 + e0 + 1], v1);
        }
        int d = (cin & 1) * 2;
        int bh = (b << 1) | half;
        int idx = ((bh * TOK + t) << 2) + d;
        if (kind == 1) {
            *(float2*)(g_q + idx) = make_float2(v0 * SCALE_LOG2E, v1 * SCALE_LOG2E);
        } else if (kind == 2) {
            *(float2*)(g_k + idx) = make_float2(v0, v1);
            __half2* khp = (__half2*)g_kh;
            khp[((bh * TOK + t) << 2) + d]     = __float2half2_rn(v0);
            khp[((bh * TOK + t) << 2) + d + 1] = __float2half2_rn(v1);
        } else {
            *(float2*)(g_v + idx) = make_float2(v0, v1);
        }
    }
}

// ---------------- Stage 2: attention (DIAGONAL: a_n = attn[n,n] * v_n) ----------------
// Duplicated-K half2 + prescaled pos table, both copied in as uint4. HFMA2 scores,
// f16x2 EX2, f16 partials flushed every 8 rows. 8 warps x 8 queries, grid (64,4).
__global__ void __launch_bounds__(256, 2) k_attn() {
    extern __shared__ float smem[];
    uint4*   sKd = (uint4*)smem;                 // 4096 uint4 (16384 float slots)
    __half2* sP2 = (__half2*)(smem + 16384);     // 128*PP2 half2
    int bh = blockIdx.y;
    int h = bh & 1;
    const uint4* gK4 = g_kh + bh * 4096;
    for (int i = threadIdx.x; i < 4096; i += 256) sKd[i] = gK4[i];
    const uint4* gP4 = (const uint4*)(g_ph + h * 128 * PP2);
    uint4* sP4 = (uint4*)sP2;
    for (int i = threadIdx.x; i < (128 * PP2) / 4; i += 256) sP4[i] = gP4[i];
    __syncthreads();

    int warp = threadIdx.x >> 5, lane = threadIdx.x & 31;
    int mi = blockIdx.x;
    int nbase = warp * 8;
    int qbase = (mi << 6) | nbase;

    float qv[8][4];
#pragma unroll
    for (int u = 0; u < 8; u++) {
        float4 qq = *(const float4*)(g_q + (bh * TOK + qbase + u) * 4);
        qv[u][0] = qq.x; qv[u][1] = qq.y; qv[u][2] = qq.z; qv[u][3] = qq.w;
    }
    __half2 qh[4][4];
#pragma unroll
    for (int pr = 0; pr < 4; pr++)
#pragma unroll
        for (int d = 0; d < 4; d++)
            qh[pr][d] = __floats2half2_rn(qv[2 * pr][d], qv[2 * pr + 1][d]);

    int pc0a = (nbase - lane) & 63;
    int pc0b = (nbase - lane - 32) & 63;
    const __half2* pA = sP2 + (mi + 64) * PP2 + pc0a;
    const __half2* pB = sP2 + (mi + 64) * PP2 + pc0b;
    const uint4* kp = sKd + lane;

    float l[8];
#pragma unroll
    for (int u = 0; u < 8; u++) l[u] = 0.f;

#pragma unroll 1
    for (int blk = 0; blk < 8; blk++) {
        __half2 accA[4], accB[4];
#pragma unroll
        for (int pr = 0; pr < 4; pr++) {
            accA[pr] = __floats2half2_rn(0.f, 0.f);
            accB[pr] = __floats2half2_rn(0.f, 0.f);
        }
#pragma unroll
        for (int it = 0; it < 8; it++) {
            uint4 ka = kp[0];
            uint4 kb = kp[32];
            kp += 64;
            __half2 a0 = *reinterpret_cast<__half2*>(&ka.x);
            __half2 a1 = *reinterpret_cast<__half2*>(&ka.y);
            __half2 a2 = *reinterpret_cast<__half2*>(&ka.z);
            __half2 a3 = *reinterpret_cast<__half2*>(&ka.w);
            __half2 b0 = *reinterpret_cast<__half2*>(&kb.x);
            __half2 b1 = *reinterpret_cast<__half2*>(&kb.y);
            __half2 b2 = *reinterpret_cast<__half2*>(&kb.z);
            __half2 b3 = *reinterpret_cast<__half2*>(&kb.w);
#pragma unroll
            for (int pr = 0; pr < 4; pr++) {
                __half2 s = pA[2 * pr];
                s = __hfma2(qh[pr][0], a0, s);
                s = __hfma2(qh[pr][1], a1, s);
                s = __hfma2(qh[pr][2], a2, s);
                s = __hfma2(qh[pr][3], a3, s);
                accA[pr] = __hadd2(accA[pr], h2ex2(s));
                __half2 t2 = pB[2 * pr];
                t2 = __hfma2(qh[pr][0], b0, t2);
                t2 = __hfma2(qh[pr][1], b1, t2);
                t2 = __hfma2(qh[pr][2], b2, t2);
                t2 = __hfma2(qh[pr][3], b3, t2);
                accB[pr] = __hadd2(accB[pr], h2ex2(t2));
            }
            pA -= PP2; pB -= PP2;
        }
#pragma unroll
        for (int pr = 0; pr < 4; pr++) {
            l[2 * pr]     += __low2float(accA[pr])  + __low2float(accB[pr]);
            l[2 * pr + 1] += __high2float(accA[pr]) + __high2float(accB[pr]);
        }
    }

#pragma unroll
    for (int u = 0; u < 8; u++) {
#pragma unroll
        for (int off = 16; off > 0; off >>= 1)
            l[u] += __shfl_xor_sync(0xffffffffu, l[u], off);
    }
    if (lane == 0) {
        float pdiag = __low2float(sP2[64 * PP2]);   // scaled R[h,0,0]
#pragma unroll
        for (int u = 0; u < 8; u++) {
            int t = qbase + u;
            float4 kv = *(const float4*)(g_k + (bh * TOK + t) * 4);
            float s = pdiag;
            s = fmaf(qv[u][0], kv.x, s);
            s = fmaf(qv[u][1], kv.y, s);
            s = fmaf(qv[u][2], kv.z, s);
            s = fmaf(qv[u][3], kv.w, s);
            float w = __fdividef(ex2(s), l[u]);
            float4 vv = *(const float4*)(g_v + (bh * TOK + t) * 4);
            *(float4*)(g_a + (bh * TOK + t) * 4) =
                make_float4(w * vv.x, w * vv.y, w * vv.z, w * vv.w);
        }
    }
}

// ---------------- Stage 3: fused tail (512 thr) ----------------
// Wo proj + residual -> sx2; MLP1 + gelu -> st1 (halo); dw conv + gelu -> st2;
// MLP3 + residual -> out. Block = 4x8 interior tile, halo 6x10. grid=256.
__global__ void __launch_bounds__(512) k_tail(
        const float* __restrict__ Wo,
        const float* __restrict__ W1, const float* __restrict__ b1,
        const float* __restrict__ W2, const float* __restrict__ b2,
        const float* __restrict__ W3, const float* __restrict__ b3,
        float* __restrict__ out) {
    __shared__ float sWo[64];
    __shared__ float sW1[256];
    __shared__ float sb1[32];
    __shared__ float sW2[288];
    __shared__ float sb2[32];
    __shared__ float sW3[256];
    __shared__ float sb3[8];
    __shared__ float st1[60 * 36];
    __shared__ float st2[32 * 36];
    __shared__ float sx2[32 * 8];
    int tid = threadIdx.x;
    if (tid < 64) sWo[tid] = Wo[tid];
    if (tid < 256) sW1[tid] = W1[tid];
    if (tid < 32) sb1[tid] = b1[tid];
    if (tid < 288) sW2[tid] = W2[tid];
    if (tid < 32) sb2[tid] = b2[tid];
    if (tid < 256) sW3[tid] = W3[tid];
    if (tid < 8) sb3[tid] = b3[tid];
    __syncthreads();

    int b = blockIdx.x >> 7;
    int tile = blockIdx.x & 127;
    int ti = tile >> 3, tj = tile & 7;

    // Phase 1: Wo proj + residual + MLP1 for 60 halo tokens, 8 threads/token
    if (tid < 480) {
        int token = tid >> 3, oct = tid & 7;
        int pi = token / 10, pj = token - pi * 10;
        int row = (ti * 4 + pi - 1) & 63;
        int col = (tj * 8 + pj - 1) & 63;
        int p = (b << 12) | (row << 6) | col;
        int t = p & 4095;
        float vec[8];
#pragma unroll
        for (int h = 0; h < 2; h++) {
            float4 av = *(const float4*)(g_a + ((((b << 1) | h) * TOK + t) << 2));
            vec[h * 4 + 0] = av.x; vec[h * 4 + 1] = av.y;
            vec[h * 4 + 2] = av.z; vec[h * 4 + 3] = av.w;
        }
        float acc[8];
        float4 x1a = *(const float4*)(g_x1 + p * 8);
        float4 x1b = *(const float4*)(g_x1 + p * 8 + 4);
        acc[0] = x1a.x; acc[1] = x1a.y; acc[2] = x1a.z; acc[3] = x1a.w;
        acc[4] = x1b.x; acc[5] = x1b.y; acc[6] = x1b.z; acc[7] = x1b.w;
#pragma unroll
        for (int e = 0; e < 8; e++)
#pragma unroll
            for (int c = 0; c < 8; c++) acc[c] = fmaf(vec[e], sWo[e * 8 + c], acc[c]);
        if (oct == 0 && pi >= 1 && pi <= 4 && pj >= 1 && pj <= 8) {
            int lt = (pi - 1) * 8 + (pj - 1);
            *(float4*)(sx2 + lt * 8)     = make_float4(acc[0], acc[1], acc[2], acc[3]);
            *(float4*)(sx2 + lt * 8 + 4) = make_float4(acc[4], acc[5], acc[6], acc[7]);
        }
        float y[8];
#pragma unroll
        for (int c = 0; c < 8; c++) y[c] = acc[c] * 0.57735026918962576f;
        int e0 = oct * 4;
        float* dst = st1 + token * 36 + e0;
#pragma unroll
        for (int ee = 0; ee < 4; ee++) {
            int e = e0 + ee;
            float v = sb1[e];
#pragma unroll
            for (int c = 0; c < 8; c++) v = fmaf(y[c], sW1[c * 32 + e], v);
            dst[ee] = gelu_f(v);
        }
    }
    __syncthreads();

    // Phase 2: depthwise 3x3 conv + gelu, 32 tokens x 16 thr (2 ch each)
    {
        int tl = tid >> 4, sub = tid & 15, e0 = sub * 2;
        int li = tl >> 3, lj = tl & 7;
        float a0 = sb2[e0], a1 = sb2[e0 + 1];
#pragma unroll
        for (int di = 0; di < 3; di++) {
#pragma unroll
            for (int dj = 0; dj < 3; dj++) {
                const float* tp = st1 + ((li + di) * 10 + (lj + dj)) * 36 + e0;
                const float* wp = sW2 + (di * 3 + dj) * 32 + e0;
                a0 = fmaf(tp[0], wp[0], a0);
                a1 = fmaf(tp[1], wp[1], a1);
            }
        }
        st2[tl * 36 + e0]     = gelu_f(a0);
        st2[tl * 36 + e0 + 1] = gelu_f(a1);
    }
    __syncthreads();

    // Phase 3: MLP3 (32->8) + residual, 32 tokens x 8 thr
    if (tid < 256) {
        int tl = tid >> 3, c = tid & 7;
        int li = tl >> 3, lj = tl & 7;
        float a = sb3[c] + sx2[tl * 8 + c];
        const float* t2p = st2 + tl * 36;
#pragma unroll
        for (int q4 = 0; q4 < 8; q4++) {
            float4 tv = *(const float4*)(t2p + q4 * 4);
            int e = q4 * 4;
            a = fmaf(tv.x, sW3[(e + 0) * 8 + c], a);
            a = fmaf(tv.y, sW3[(e + 1) * 8 + c], a);
            a = fmaf(tv.z, sW3[(e + 2) * 8 + c], a);
            a = fmaf(tv.w, sW3[(e + 3) * 8 + c], a);
        }
        int p = (b << 12) | ((ti * 4 + li) << 6) | (tj * 8 + lj);
        out[p * 8 + c] = a;
    }
}

extern "C" void kernel_launch(void* const* d_in, const int* in_sizes, int n_in,
                              void* d_out, int out_size) {
    const float* x      = (const float*)d_in[0];
    const float* conv_W = (const float*)d_in[1];
    const float* conv_b = (const float*)d_in[2];
    const float* Wq     = (const float*)d_in[3];
    const float* Wk     = (const float*)d_in[4];
    const float* Wv     = (const float*)d_in[5];
    const float* pos    = (const float*)d_in[6];
    const float* Wo     = (const float*)d_in[7];
    const float* m1W    = (const float*)d_in[8];
    const float* m1b    = (const float*)d_in[9];
    const float* m2W    = (const float*)d_in[10];
    const float* m2b    = (const float*)d_in[11];
    const float* m3W    = (const float*)d_in[12];
    const float* m3b    = (const float*)d_in[13];
    float* out = (float*)d_out;

    const int ATTN_SMEM = (16384 + 128 * PP2) * 4;   // 102400 bytes
    cudaFuncSetAttribute(k_attn, cudaFuncAttributeMaxDynamicSharedMemorySize, ATTN_SMEM);

    k_conv_qkv<<<256, 512>>>(x, conv_W, conv_b, Wq, Wk, Wv, pos);
    dim3 ag(64, 4);
    k_attn<<<ag, 256, ATTN_SMEM>>>();
    k_tail<<<256, 512>>>(Wo, m1W, m1b, m2W, m2b, m3W, m3b, out);
}

// round 11
// speedup vs baseline: 1.0517x; 1.0517x over previous
#include <cuda_runtime.h>
#include <cuda_fp16.h>
#include <math.h>

// Problem constants: B=2, M=N=64, H=2, C=8, D=4
#define TOK  4096
#define TOT  8192

#define SCALE_LOG2E 0.72134752044448170f   // 0.5 * log2(e)
#define PP2 70                              // pos half2 row pitch

// Scratch (allocation-free: __device__ globals)
__device__ float g_x1[65536];
__device__ float g_q[65536];       // [bh][t][d], pre-scaled by 0.5*log2e
__device__ float g_k[65536];
__device__ float g_v[65536];
__device__ float g_a[65536];

__device__ __forceinline__ float gelu_f(float x) {
    float z2 = 1.5957691216057308f * fmaf(0.044715f, x * x * x, x);  // 2z
    return __fdividef(x, 1.0f + __expf(-z2));
}
__device__ __forceinline__ float ex2(float x) {
    float r; asm("ex2.approx.ftz.f32 %0, %1;" : "=f"(r) : "f"(x)); return r;
}
__device__ __forceinline__ __half2 h2ex2(__half2 x) {
    __half2 r;
    asm("ex2.approx.f16x2 %0, %1;"
        : "=r"(*reinterpret_cast<unsigned*>(&r))
        : "r"(*reinterpret_cast<const unsigned*>(&x)));
    return r;
}

// ---------------- Stage 1: gelu + circular conv (8->8) + residual + QKV ----------------
// 4x8 token tile, 8 threads/token (1 input channel each), 3 shfl-reduce rounds. grid=256.
__global__ void __launch_bounds__(256) k_conv_qkv(
        const float* __restrict__ x, const float* __restrict__ W,
        const float* __restrict__ bias, const float* __restrict__ Wq,
        const float* __restrict__ Wk, const float* __restrict__ Wv) {
    __shared__ float sW[576];
    __shared__ float sb[8];
    __shared__ float sQKV[192];
    __shared__ float sX[60 * 8];   // 6x10 halo gelu tile
    for (int i = threadIdx.x; i < 576; i += 256) sW[i] = W[i];
    if (threadIdx.x < 8) sb[threadIdx.x] = bias[threadIdx.x];
    if (threadIdx.x < 64) {
        sQKV[threadIdx.x]       = Wq[threadIdx.x];
        sQKV[64 + threadIdx.x]  = Wk[threadIdx.x];
        sQKV[128 + threadIdx.x] = Wv[threadIdx.x];
    }
    int b = blockIdx.x >> 7;
    int tile = blockIdx.x & 127;
    int ti = tile >> 3, tj = tile & 7;
    // gelu the 6x10 halo (480 channel-cells)
    for (int u = threadIdx.x; u < 480; u += 256) {
        int cell = u >> 3, ch = u & 7;
        int pi = cell / 10, pj = cell - pi * 10;
        int row = (ti * 4 + pi - 1) & 63;
        int col = (tj * 8 + pj - 1) & 63;
        sX[u] = gelu_f(x[((((b << 12) | (row << 6)) | col) << 3) + ch]);
    }
    __syncthreads();

    int tl = threadIdx.x >> 3, cin = threadIdx.x & 7;
    int li = tl >> 3, lj = tl & 7;
    int p = (b << 12) | ((ti * 4 + li) << 6) | (tj * 8 + lj);
    float acc[8];
#pragma unroll
    for (int c = 0; c < 8; c++) acc[c] = 0.f;
#pragma unroll
    for (int di = 0; di < 3; di++) {
#pragma unroll
        for (int dj = 0; dj < 3; dj++) {
            float xv = sX[((li + di) * 10 + (lj + dj)) * 8 + cin];
            const float* wp = sW + (di * 3 + dj) * 64 + cin * 8;
#pragma unroll
            for (int c = 0; c < 8; c++) acc[c] = fmaf(xv, wp[c], acc[c]);
        }
    }
    if (cin == 0) {   // fold bias + residual once
        float4 xa = *(const float4*)(x + p * 8);
        float4 xb = *(const float4*)(x + p * 8 + 4);
        acc[0] += sb[0] + xa.x; acc[1] += sb[1] + xa.y;
        acc[2] += sb[2] + xa.z; acc[3] += sb[3] + xa.w;
        acc[4] += sb[4] + xb.x; acc[5] += sb[5] + xb.y;
        acc[6] += sb[6] + xb.z; acc[7] += sb[7] + xb.w;
    }
#pragma unroll
    for (int c = 0; c < 8; c++) acc[c] += __shfl_xor_sync(0xffffffffu, acc[c], 1);
#pragma unroll
    for (int c = 0; c < 8; c++) acc[c] += __shfl_xor_sync(0xffffffffu, acc[c], 2);
#pragma unroll
    for (int c = 0; c < 8; c++) acc[c] += __shfl_xor_sync(0xffffffffu, acc[c], 4);

    int t = p & 4095;
    int e = cin;
    g_x1[p * 8 + e] = acc[e];
    float y[8];
#pragma unroll
    for (int c = 0; c < 8; c++) y[c] = acc[c] * 0.70710678118654752f;
    float qe = 0.f, ke = 0.f, ve = 0.f;
#pragma unroll
    for (int c = 0; c < 8; c++) {
        qe = fmaf(y[c], sQKV[c * 8 + e], qe);
        ke = fmaf(y[c], sQKV[64 + c * 8 + e], ke);
        ve = fmaf(y[c], sQKV[128 + c * 8 + e], ve);
    }
    int h = e >> 2, d = e & 3;
    int idx = ((((b << 1) | h) * TOK + t) << 2) + d;
    g_q[idx] = qe * SCALE_LOG2E;
    g_k[idx] = ke;
    g_v[idx] = ve;
}

// ---------------- Stage 2: attention (DIAGONAL: a_n = attn[n,n] * v_n) ----------------
// Full half2 pipeline. 8 warps x 8 queries; grid=(64, 4), 256 thr.
__global__ void __launch_bounds__(256, 2) k_attn(const float* __restrict__ pos) {
    extern __shared__ float smem[];
    __half2* sK2 = (__half2*)smem;                     // 4096 keys x 2 half2
    __half2* sP2 = (__half2*)(smem + 8192);            // 128 x PP2 (rows doubled)
    int bh = blockIdx.y;
    int h = bh & 1;
    const float* gP = pos + h * 4096;
    const float4* gK = (const float4*)(g_k + bh * (TOK * 4));
    for (int i = threadIdx.x; i < 4096; i += 256) {
        float4 kv = gK[i];
        sK2[i * 2]     = __floats2half2_rn(kv.x, kv.y);
        sK2[i * 2 + 1] = __floats2half2_rn(kv.z, kv.w);
    }
    for (int i = threadIdx.x; i < 128 * PP2; i += 256) {
        int r = i / PP2, c = i - r * PP2;
        int row = (r & 63) << 6;
        sP2[i] = __floats2half2_rn(gP[row + (c & 63)] * SCALE_LOG2E,
                                   gP[row + ((c + 1) & 63)] * SCALE_LOG2E);
    }
    __syncthreads();

    int warp = threadIdx.x >> 5, lane = threadIdx.x & 31;
    int mi = blockIdx.x;
    int nbase = warp * 8;
    int qbase = (mi << 6) | nbase;

    float qv[8][4];
#pragma unroll
    for (int u = 0; u < 8; u++) {
        float4 qq = *(const float4*)(g_q + (bh * TOK + qbase + u) * 4);
        qv[u][0] = qq.x; qv[u][1] = qq.y; qv[u][2] = qq.z; qv[u][3] = qq.w;
    }
    __half2 qh[4][4];
#pragma unroll
    for (int pr = 0; pr < 4; pr++)
#pragma unroll
        for (int d = 0; d < 4; d++)
            qh[pr][d] = __floats2half2_rn(qv[2 * pr][d], qv[2 * pr + 1][d]);

    int pc0a = (nbase - lane) & 63;
    int pc0b = (nbase - lane - 32) & 63;
    const __half2* pA = sP2 + (mi + 64) * PP2 + pc0a;
    const __half2* pB = sP2 + (mi + 64) * PP2 + pc0b;
    const uint2* kp = (const uint2*)sK2 + lane;

    float l[8];
#pragma unroll
    for (int u = 0; u < 8; u++) l[u] = 0.f;

#pragma unroll 1
    for (int blk = 0; blk < 8; blk++) {
        __half2 accA[4], accB[4];
#pragma unroll
        for (int pr = 0; pr < 4; pr++) {
            accA[pr] = __floats2half2_rn(0.f, 0.f);
            accB[pr] = __floats2half2_rn(0.f, 0.f);
        }
#pragma unroll
        for (int it = 0; it < 8; it++) {
            uint2 ka = kp[0];
            uint2 kb = kp[32];
            kp += 64;
            __half2 ka01 = *reinterpret_cast<__half2*>(&ka.x);
            __half2 ka23 = *reinterpret_cast<__half2*>(&ka.y);
            __half2 kb01 = *reinterpret_cast<__half2*>(&kb.x);
            __half2 kb23 = *reinterpret_cast<__half2*>(&kb.y);
            __half2 a0 = __low2half2(ka01), a1 = __high2half2(ka01);
            __half2 a2 = __low2half2(ka23), a3 = __high2half2(ka23);
            __half2 b0 = __low2half2(kb01), b1 = __high2half2(kb01);
            __half2 b2 = __low2half2(kb23), b3 = __high2half2(kb23);
#pragma unroll
            for (int pr = 0; pr < 4; pr++) {
                __half2 s = pA[2 * pr];
                s = __hfma2(qh[pr][0], a0, s);
                s = __hfma2(qh[pr][1], a1, s);
                s = __hfma2(qh[pr][2], a2, s);
                s = __hfma2(qh[pr][3], a3, s);
                accA[pr] = __hadd2(accA[pr], h2ex2(s));
                __half2 t2 = pB[2 * pr];
                t2 = __hfma2(qh[pr][0], b0, t2);
                t2 = __hfma2(qh[pr][1], b1, t2);
                t2 = __hfma2(qh[pr][2], b2, t2);
                t2 = __hfma2(qh[pr][3], b3, t2);
                accB[pr] = __hadd2(accB[pr], h2ex2(t2));
            }
            pA -= PP2; pB -= PP2;
        }
#pragma unroll
        for (int pr = 0; pr < 4; pr++) {
            l[2 * pr]     += __low2float(accA[pr])  + __low2float(accB[pr]);
            l[2 * pr + 1] += __high2float(accA[pr]) + __high2float(accB[pr]);
        }
    }

#pragma unroll
    for (int u = 0; u < 8; u++) {
#pragma unroll
        for (int off = 16; off > 0; off >>= 1)
            l[u] += __shfl_xor_sync(0xffffffffu, l[u], off);
    }
    if (lane == 0) {
        float pdiag = gP[0] * SCALE_LOG2E;
#pragma unroll
        for (int u = 0; u < 8; u++) {
            int t = qbase + u;
            float4 kv = *(const float4*)(g_k + (bh * TOK + t) * 4);
            float s = pdiag;
            s = fmaf(qv[u][0], kv.x, s);
            s = fmaf(qv[u][1], kv.y, s);
            s = fmaf(qv[u][2], kv.z, s);
            s = fmaf(qv[u][3], kv.w, s);
            float w = __fdividef(ex2(s), l[u]);
            float4 vv = *(const float4*)(g_v + (bh * TOK + t) * 4);
            *(float4*)(g_a + (bh * TOK + t) * 4) =
                make_float4(w * vv.x, w * vv.y, w * vv.z, w * vv.w);
        }
    }
}

// ---------------- Stage 3: fused tail (512 thr) ----------------
// Wo proj + residual -> sx2; MLP1 + gelu -> st1 (halo); dw conv + gelu -> st2;
// MLP3 + residual -> out. Block = 4x8 interior tile, halo 6x10. grid=256.
__global__ void __launch_bounds__(512) k_tail(
        const float* __restrict__ Wo,
        const float* __restrict__ W1, const float* __restrict__ b1,
        const float* __restrict__ W2, const float* __restrict__ b2,
        const float* __restrict__ W3, const float* __restrict__ b3,
        float* __restrict__ out) {
    __shared__ float sWo[64];
    __shared__ float sW1[256];
    __shared__ float sb1[32];
    __shared__ float sW2[288];
    __shared__ float sb2[32];
    __shared__ float sW3[256];
    __shared__ float sb3[8];
    __shared__ float st1[60 * 36];
    __shared__ float st2[32 * 36];
    __shared__ float sx2[32 * 8];
    int tid = threadIdx.x;
    if (tid < 64) sWo[tid] = Wo[tid];
    if (tid < 256) sW1[tid] = W1[tid];
    if (tid < 32) sb1[tid] = b1[tid];
    if (tid < 288) sW2[tid] = W2[tid];
    if (tid < 32) sb2[tid] = b2[tid];
    if (tid < 256) sW3[tid] = W3[tid];
    if (tid < 8) sb3[tid] = b3[tid];
    __syncthreads();

    int b = blockIdx.x >> 7;
    int tile = blockIdx.x & 127;
    int ti = tile >> 3, tj = tile & 7;

    // Phase 1: Wo proj + residual + MLP1 for 60 halo tokens, 8 threads/token
    if (tid < 480) {
        int token = tid >> 3, oct = tid & 7;
        int pi = token / 10, pj = token - pi * 10;
        int row = (ti * 4 + pi - 1) & 63;
        int col = (tj * 8 + pj - 1) & 63;
        int p = (b << 12) | (row << 6) | col;
        int t = p & 4095;
        float vec[8];
#pragma unroll
        for (int h = 0; h < 2; h++) {
            float4 av = *(const float4*)(g_a + ((((b << 1) | h) * TOK + t) << 2));
            vec[h * 4 + 0] = av.x; vec[h * 4 + 1] = av.y;
            vec[h * 4 + 2] = av.z; vec[h * 4 + 3] = av.w;
        }
        float acc[8];
        float4 x1a = *(const float4*)(g_x1 + p * 8);
        float4 x1b = *(const float4*)(g_x1 + p * 8 + 4);
        acc[0] = x1a.x; acc[1] = x1a.y; acc[2] = x1a.z; acc[3] = x1a.w;
        acc[4] = x1b.x; acc[5] = x1b.y; acc[6] = x1b.z; acc[7] = x1b.w;
#pragma unroll
        for (int e = 0; e < 8; e++)
#pragma unroll
            for (int c = 0; c < 8; c++) acc[c] = fmaf(vec[e], sWo[e * 8 + c], acc[c]);
        if (oct == 0 && pi >= 1 && pi <= 4 && pj >= 1 && pj <= 8) {
            int lt = (pi - 1) * 8 + (pj - 1);
            *(float4*)(sx2 + lt * 8)     = make_float4(acc[0], acc[1], acc[2], acc[3]);
            *(float4*)(sx2 + lt * 8 + 4) = make_float4(acc[4], acc[5], acc[6], acc[7]);
        }
        float y[8];
#pragma unroll
        for (int c = 0; c < 8; c++) y[c] = acc[c] * 0.57735026918962576f;
        int e0 = oct * 4;
        float* dst = st1 + token * 36 + e0;
#pragma unroll
        for (int ee = 0; ee < 4; ee++) {
            int e = e0 + ee;
            float v = sb1[e];
#pragma unroll
            for (int c = 0; c < 8; c++) v = fmaf(y[c], sW1[c * 32 + e], v);
            dst[ee] = gelu_f(v);
        }
    }
    __syncthreads();

    // Phase 2: depthwise 3x3 conv + gelu, 32 tokens x 16 thr (2 ch each)
    {
        int tl = tid >> 4, sub = tid & 15, e0 = sub * 2;
        int li = tl >> 3, lj = tl & 7;
        float a0 = sb2[e0], a1 = sb2[e0 + 1];
#pragma unroll
        for (int di = 0; di < 3; di++) {
#pragma unroll
            for (int dj = 0; dj < 3; dj++) {
                const float* tp = st1 + ((li + di) * 10 + (lj + dj)) * 36 + e0;
                const float* wp = sW2 + (di * 3 + dj) * 32 + e0;
                a0 = fmaf(tp[0], wp[0], a0);
                a1 = fmaf(tp[1], wp[1], a1);
            }
        }
        st2[tl * 36 + e0]     = gelu_f(a0);
        st2[tl * 36 + e0 + 1] = gelu_f(a1);
    }
    __syncthreads();

    // Phase 3: MLP3 (32->8) + residual, 32 tokens x 8 thr
    if (tid < 256) {
        int tl = tid >> 3, c = tid & 7;
        int li = tl >> 3, lj = tl & 7;
        float a = sb3[c] + sx2[tl * 8 + c];
        const float* t2p = st2 + tl * 36;
#pragma unroll
        for (int q4 = 0; q4 < 8; q4++) {
            float4 tv = *(const float4*)(t2p + q4 * 4);
            int e = q4 * 4;
            a = fmaf(tv.x, sW3[(e + 0) * 8 + c], a);
            a = fmaf(tv.y, sW3[(e + 1) * 8 + c], a);
            a = fmaf(tv.z, sW3[(e + 2) * 8 + c], a);
            a = fmaf(tv.w, sW3[(e + 3) * 8 + c], a);
        }
        int p = (b << 12) | ((ti * 4 + li) << 6) | (tj * 8 + lj);
        out[p * 8 + c] = a;
    }
}

extern "C" void kernel_launch(void* const* d_in, const int* in_sizes, int n_in,
                              void* d_out, int out_size) {
    const float* x      = (const float*)d_in[0];
    const float* conv_W = (const float*)d_in[1];
    const float* conv_b = (const float*)d_in[2];
    const float* Wq     = (const float*)d_in[3];
    const float* Wk     = (const float*)d_in[4];
    const float* Wv     = (const float*)d_in[5];
    const float* pos    = (const float*)d_in[6];
    const float* Wo     = (const float*)d_in[7];
    const float* m1W    = (const float*)d_in[8];
    const float* m1b    = (const float*)d_in[9];
    const float* m2W    = (const float*)d_in[10];
    const float* m2b    = (const float*)d_in[11];
    const float* m3W    = (const float*)d_in[12];
    const float* m3b    = (const float*)d_in[13];
    float* out = (float*)d_out;

    const int ATTN_SMEM = (8192 + 128 * PP2) * 4;   // 68608 bytes
    cudaFuncSetAttribute(k_attn, cudaFuncAttributeMaxDynamicSharedMemorySize, ATTN_SMEM);

    k_conv_qkv<<<256, 256>>>(x, conv_W, conv_b, Wq, Wk, Wv);
    dim3 ag(64, 4);
    k_attn<<<ag, 256, ATTN_SMEM>>>(pos);
    k_tail<<<256, 512>>>(Wo, m1W, m1b, m2W, m2b, m3W, m3b, out);
}

// round 12
// speedup vs baseline: 1.1519x; 1.0953x over previous
#include <cuda_runtime.h>
#include <cuda_fp16.h>
#include <math.h>

// Problem constants: B=2, M=N=64, H=2, C=8, D=4
#define TOK  4096
#define TOT  8192

#define SCALE_LOG2E 0.72134752044448170f   // 0.5 * log2(e)

// Scratch (allocation-free: __device__ globals)
__device__ float g_x1[65536];
__device__ float g_q[65536];       // [bh][t][d], pre-scaled by 0.5*log2e
__device__ float g_k[65536];
__device__ float g_v[65536];
__device__ float g_l2[32768];      // [kh][bh][t] partial softmax denominators

__device__ __forceinline__ float gelu_f(float x) {
    float z2 = 1.5957691216057308f * fmaf(0.044715f, x * x * x, x);  // 2z
    return __fdividef(x, 1.0f + __expf(-z2));
}
__device__ __forceinline__ float ex2(float x) {
    float r; asm("ex2.approx.ftz.f32 %0, %1;" : "=f"(r) : "f"(x)); return r;
}
__device__ __forceinline__ __half2 h2ex2(__half2 x) {
    __half2 r;
    asm("ex2.approx.f16x2 %0, %1;"
        : "=r"(*reinterpret_cast<unsigned*>(&r))
        : "r"(*reinterpret_cast<const unsigned*>(&x)));
    return r;
}
__device__ __forceinline__ unsigned h2u(__half2 h) {
    return *reinterpret_cast<unsigned*>(&h);
}

// ---------------- Stage 1: gelu + circular conv (8->8) + residual + QKV ----------------
// 4x8 token tile, 8 threads/token (1 input channel each), 3 shfl-reduce rounds. grid=256.
__global__ void __launch_bounds__(256) k_conv_qkv(
        const float* __restrict__ x, const float* __restrict__ W,
        const float* __restrict__ bias, const float* __restrict__ Wq,
        const float* __restrict__ Wk, const float* __restrict__ Wv) {
    __shared__ float sW[576];
    __shared__ float sb[8];
    __shared__ float sQKV[192];
    __shared__ float sX[60 * 8];   // 6x10 halo gelu tile
    for (int i = threadIdx.x; i < 576; i += 256) sW[i] = W[i];
    if (threadIdx.x < 8) sb[threadIdx.x] = bias[threadIdx.x];
    if (threadIdx.x < 64) {
        sQKV[threadIdx.x]       = Wq[threadIdx.x];
        sQKV[64 + threadIdx.x]  = Wk[threadIdx.x];
        sQKV[128 + threadIdx.x] = Wv[threadIdx.x];
    }
    int b = blockIdx.x >> 7;
    int tile = blockIdx.x & 127;
    int ti = tile >> 3, tj = tile & 7;
    for (int u = threadIdx.x; u < 480; u += 256) {
        int cell = u >> 3, ch = u & 7;
        int pi = cell / 10, pj = cell - pi * 10;
        int row = (ti * 4 + pi - 1) & 63;
        int col = (tj * 8 + pj - 1) & 63;
        sX[u] = gelu_f(x[((((b << 12) | (row << 6)) | col) << 3) + ch]);
    }
    __syncthreads();

    int tl = threadIdx.x >> 3, cin = threadIdx.x & 7;
    int li = tl >> 3, lj = tl & 7;
    int p = (b << 12) | ((ti * 4 + li) << 6) | (tj * 8 + lj);
    float acc[8];
#pragma unroll
    for (int c = 0; c < 8; c++) acc[c] = 0.f;
#pragma unroll
    for (int di = 0; di < 3; di++) {
#pragma unroll
        for (int dj = 0; dj < 3; dj++) {
            float xv = sX[((li + di) * 10 + (lj + dj)) * 8 + cin];
            const float* wp = sW + (di * 3 + dj) * 64 + cin * 8;
#pragma unroll
            for (int c = 0; c < 8; c++) acc[c] = fmaf(xv, wp[c], acc[c]);
        }
    }
    if (cin == 0) {
        float4 xa = *(const float4*)(x + p * 8);
        float4 xb = *(const float4*)(x + p * 8 + 4);
        acc[0] += sb[0] + xa.x; acc[1] += sb[1] + xa.y;
        acc[2] += sb[2] + xa.z; acc[3] += sb[3] + xa.w;
        acc[4] += sb[4] + xb.x; acc[5] += sb[5] + xb.y;
        acc[6] += sb[6] + xb.z; acc[7] += sb[7] + xb.w;
    }
#pragma unroll
    for (int c = 0; c < 8; c++) acc[c] += __shfl_xor_sync(0xffffffffu, acc[c], 1);
#pragma unroll
    for (int c = 0; c < 8; c++) acc[c] += __shfl_xor_sync(0xffffffffu, acc[c], 2);
#pragma unroll
    for (int c = 0; c < 8; c++) acc[c] += __shfl_xor_sync(0xffffffffu, acc[c], 4);

    int t = p & 4095;
    int e = cin;
    g_x1[p * 8 + e] = acc[e];
    float y[8];
#pragma unroll
    for (int c = 0; c < 8; c++) y[c] = acc[c] * 0.70710678118654752f;
    float qe = 0.f, ke = 0.f, ve = 0.f;
#pragma unroll
    for (int c = 0; c < 8; c++) {
        qe = fmaf(y[c], sQKV[c * 8 + e], qe);
        ke = fmaf(y[c], sQKV[64 + c * 8 + e], ke);
        ve = fmaf(y[c], sQKV[128 + c * 8 + e], ve);
    }
    int h = e >> 2, d = e & 3;
    int idx = ((((b << 1) | h) * TOK + t) << 2) + d;
    g_q[idx] = qe * SCALE_LOG2E;
    g_k[idx] = ke;
    g_v[idx] = ve;
}

// ---------------- Stage 2: attention partial denominators ----------------
// Key-split: grid (128, 4): blockIdx.x = mi*2 + kh; each CTA does 32 mj rows
// (2048 keys) for 64 queries. Pos quad table: QT[rb][c] = uint4 of 4 half2 biases
// for queries 0..7 at col offset c (one aligned LDS.128 per class per row).
__global__ void __launch_bounds__(256) k_attn(const float* __restrict__ pos) {
    extern __shared__ float smem[];
    __half2* sK2 = (__half2*)smem;          // 2048 keys x 2 half2 (16 KB)
    uint4*   sQT = (uint4*)(smem + 4096);   // 32 rows x 64 entries (32 KB)
    int mi = blockIdx.x >> 1, kh = blockIdx.x & 1;
    int bh = blockIdx.y, h = bh & 1;
    const float* gP = pos + h * 4096;

    const float4* gK = (const float4*)(g_k + ((bh * TOK + kh * 2048) << 2));
    for (int i = threadIdx.x; i < 2048; i += 256) {
        float4 kv = gK[i];
        sK2[i * 2]     = __floats2half2_rn(kv.x, kv.y);
        sK2[i * 2 + 1] = __floats2half2_rn(kv.z, kv.w);
    }
    int rowbase = mi - kh * 32;
    for (int u = threadIdx.x; u < 32 * 64; u += 256) {
        int rb = u >> 6, c = u & 63;
        const float* pr = gP + (((rowbase - rb) & 63) << 6);
        __half2 p0 = __floats2half2_rn(pr[c] * SCALE_LOG2E,            pr[(c + 1) & 63] * SCALE_LOG2E);
        __half2 p1 = __floats2half2_rn(pr[(c + 2) & 63] * SCALE_LOG2E, pr[(c + 3) & 63] * SCALE_LOG2E);
        __half2 p2 = __floats2half2_rn(pr[(c + 4) & 63] * SCALE_LOG2E, pr[(c + 5) & 63] * SCALE_LOG2E);
        __half2 p3 = __floats2half2_rn(pr[(c + 6) & 63] * SCALE_LOG2E, pr[(c + 7) & 63] * SCALE_LOG2E);
        uint4 ent; ent.x = h2u(p0); ent.y = h2u(p1); ent.z = h2u(p2); ent.w = h2u(p3);
        sQT[u] = ent;
    }
    __syncthreads();

    int warp = threadIdx.x >> 5, lane = threadIdx.x & 31;
    int nbase = warp * 8;
    int qbase = (mi << 6) | nbase;

    __half2 qh[4][4];
#pragma unroll
    for (int pr2 = 0; pr2 < 4; pr2++) {
        float4 qa = *(const float4*)(g_q + (bh * TOK + qbase + 2 * pr2) * 4);
        float4 qb = *(const float4*)(g_q + (bh * TOK + qbase + 2 * pr2 + 1) * 4);
        qh[pr2][0] = __floats2half2_rn(qa.x, qb.x);
        qh[pr2][1] = __floats2half2_rn(qa.y, qb.y);
        qh[pr2][2] = __floats2half2_rn(qa.z, qb.z);
        qh[pr2][3] = __floats2half2_rn(qa.w, qb.w);
    }

    int c0 = (nbase - lane) & 63;
    const uint4* qtA = sQT + c0;
    const uint4* qtB = sQT + (c0 ^ 32);
    const uint2* kp = (const uint2*)sK2 + lane;

    float l[8];
#pragma unroll
    for (int u = 0; u < 8; u++) l[u] = 0.f;

#pragma unroll 1
    for (int blk = 0; blk < 4; blk++) {
        __half2 accA[4], accB[4];
#pragma unroll
        for (int pr2 = 0; pr2 < 4; pr2++) {
            accA[pr2] = __floats2half2_rn(0.f, 0.f);
            accB[pr2] = __floats2half2_rn(0.f, 0.f);
        }
#pragma unroll
        for (int it = 0; it < 8; it++) {
            uint2 ka = kp[it * 64];
            uint2 kb = kp[it * 64 + 32];
            uint4 pa = qtA[it * 64];
            uint4 pb = qtB[it * 64];
            __half2 ka01 = *reinterpret_cast<__half2*>(&ka.x);
            __half2 ka23 = *reinterpret_cast<__half2*>(&ka.y);
            __half2 kb01 = *reinterpret_cast<__half2*>(&kb.x);
            __half2 kb23 = *reinterpret_cast<__half2*>(&kb.y);
            __half2 a0 = __low2half2(ka01), a1 = __high2half2(ka01);
            __half2 a2 = __low2half2(ka23), a3 = __high2half2(ka23);
            __half2 b0 = __low2half2(kb01), b1 = __high2half2(kb01);
            __half2 b2 = __low2half2(kb23), b3 = __high2half2(kb23);
            const unsigned* pav = &pa.x;
            const unsigned* pbv = &pb.x;
#pragma unroll
            for (int pr2 = 0; pr2 < 4; pr2++) {
                __half2 s = *reinterpret_cast<const __half2*>(&pav[pr2]);
                s = __hfma2(qh[pr2][0], a0, s);
                s = __hfma2(qh[pr2][1], a1, s);
                s = __hfma2(qh[pr2][2], a2, s);
                s = __hfma2(qh[pr2][3], a3, s);
                accA[pr2] = __hadd2(accA[pr2], h2ex2(s));
                __half2 t2 = *reinterpret_cast<const __half2*>(&pbv[pr2]);
                t2 = __hfma2(qh[pr2][0], b0, t2);
                t2 = __hfma2(qh[pr2][1], b1, t2);
                t2 = __hfma2(qh[pr2][2], b2, t2);
                t2 = __hfma2(qh[pr2][3], b3, t2);
                accB[pr2] = __hadd2(accB[pr2], h2ex2(t2));
            }
        }
        kp += 512; qtA += 512; qtB += 512;
#pragma unroll
        for (int pr2 = 0; pr2 < 4; pr2++) {
            l[2 * pr2]     += __low2float(accA[pr2])  + __low2float(accB[pr2]);
            l[2 * pr2 + 1] += __high2float(accA[pr2]) + __high2float(accB[pr2]);
        }
    }

#pragma unroll
    for (int u = 0; u < 8; u++) {
#pragma unroll
        for (int off = 16; off > 0; off >>= 1)
            l[u] += __shfl_xor_sync(0xffffffffu, l[u], off);
    }
    if (lane == 0) {
        float* dst = g_l2 + ((kh * 4 + bh) << 12) + qbase;
        dst[0] = l[0]; dst[1] = l[1]; dst[2] = l[2]; dst[3] = l[3];
        dst[4] = l[4]; dst[5] = l[5]; dst[6] = l[6]; dst[7] = l[7];
    }
}

// ---------------- Stage 3: fused tail (256 thr) ----------------
// Attention normalize (diagonal) + Wo proj + residual -> sx2; MLP1 + gelu -> st1 (halo);
// dw conv + gelu -> st2; MLP3 + residual -> out. 4x8 interior tile, halo 6x10. grid=256.
__global__ void __launch_bounds__(256) k_tail(
        const float* __restrict__ pos,
        const float* __restrict__ Wo,
        const float* __restrict__ W1, const float* __restrict__ b1,
        const float* __restrict__ W2, const float* __restrict__ b2,
        const float* __restrict__ W3, const float* __restrict__ b3,
        float* __restrict__ out) {
    __shared__ float sWo[64];
    __shared__ float sW1[256];
    __shared__ float sb1[32];
    __shared__ float sW2[288];
    __shared__ float sb2[32];
    __shared__ float sW3[256];
    __shared__ float sb3[8];
    __shared__ float st1[60 * 36];
    __shared__ float st2[32 * 36];
    __shared__ float sx2[32 * 8];
    int tid = threadIdx.x;
    if (tid < 64) sWo[tid] = Wo[tid];
    sW1[tid] = W1[tid];
    if (tid < 32) sb1[tid] = b1[tid];
    sW2[tid] = W2[tid];
    if (tid < 32) sW2[256 + tid] = W2[256 + tid];
    if (tid < 32) sb2[tid] = b2[tid];
    sW3[tid] = W3[tid];
    if (tid < 8) sb3[tid] = b3[tid];
    __syncthreads();

    int b = blockIdx.x >> 7;
    int tile = blockIdx.x & 127;
    int ti = tile >> 3, tj = tile & 7;

    // Phase 1: attention normalize + Wo proj + residual + MLP1, 60 halo tokens x 4 thr
    if (tid < 240) {
        int token = tid >> 2, quarter = tid & 3;
        int pi = token / 10, pj = token - pi * 10;
        int row = (ti * 4 + pi - 1) & 63;
        int col = (tj * 8 + pj - 1) & 63;
        int p = (b << 12) | (row << 6) | col;
        int t = p & 4095;
        float vec[8];
#pragma unroll
        for (int hh = 0; hh < 2; hh++) {
            int bh = (b << 1) | hh;
            int base = (bh * TOK + t) << 2;
            float4 q = *(const float4*)(g_q + base);
            float4 k = *(const float4*)(g_k + base);
            float4 v = *(const float4*)(g_v + base);
            float lsum = g_l2[(bh << 12) + t] + g_l2[16384 + (bh << 12) + t];
            float s = pos[hh * 4096] * SCALE_LOG2E;   // diagonal bias R[h,0,0]
            s = fmaf(q.x, k.x, s);
            s = fmaf(q.y, k.y, s);
            s = fmaf(q.z, k.z, s);
            s = fmaf(q.w, k.w, s);
            float w = __fdividef(ex2(s), lsum);
            vec[hh * 4 + 0] = w * v.x; vec[hh * 4 + 1] = w * v.y;
            vec[hh * 4 + 2] = w * v.z; vec[hh * 4 + 3] = w * v.w;
        }
        float acc[8];
        float4 x1a = *(const float4*)(g_x1 + p * 8);
        float4 x1b = *(const float4*)(g_x1 + p * 8 + 4);
        acc[0] = x1a.x; acc[1] = x1a.y; acc[2] = x1a.z; acc[3] = x1a.w;
        acc[4] = x1b.x; acc[5] = x1b.y; acc[6] = x1b.z; acc[7] = x1b.w;
#pragma unroll
        for (int e = 0; e < 8; e++)
#pragma unroll
            for (int c = 0; c < 8; c++) acc[c] = fmaf(vec[e], sWo[e * 8 + c], acc[c]);
        if (quarter == 0 && pi >= 1 && pi <= 4 && pj >= 1 && pj <= 8) {
            int lt = (pi - 1) * 8 + (pj - 1);
            *(float4*)(sx2 + lt * 8)     = make_float4(acc[0], acc[1], acc[2], acc[3]);
            *(float4*)(sx2 + lt * 8 + 4) = make_float4(acc[4], acc[5], acc[6], acc[7]);
        }
        float y[8];
#pragma unroll
        for (int c = 0; c < 8; c++) y[c] = acc[c] * 0.57735026918962576f;
        int e0 = quarter * 8;
        float* dst = st1 + token * 36 + e0;
#pragma unroll
        for (int ee = 0; ee < 8; ee++) {
            int e = e0 + ee;
            float v = sb1[e];
#pragma unroll
            for (int c = 0; c < 8; c++) v = fmaf(y[c], sW1[c * 32 + e], v);
            dst[ee] = gelu_f(v);
        }
    }
    __syncthreads();

    // Phase 2: depthwise 3x3 conv + gelu, 32 tokens x 8 thr (4 ch each)
    int tl = tid >> 3, sub = tid & 7, e0 = sub * 4;
    int li = tl >> 3, lj = tl & 7;
    {
        float acc[4];
#pragma unroll
        for (int ee = 0; ee < 4; ee++) acc[ee] = sb2[e0 + ee];
#pragma unroll
        for (int di = 0; di < 3; di++) {
#pragma unroll
            for (int dj = 0; dj < 3; dj++) {
                const float* tp = st1 + ((li + di) * 10 + (lj + dj)) * 36 + e0;
                const float* wp = sW2 + (di * 3 + dj) * 32 + e0;
                acc[0] = fmaf(tp[0], wp[0], acc[0]);
                acc[1] = fmaf(tp[1], wp[1], acc[1]);
                acc[2] = fmaf(tp[2], wp[2], acc[2]);
                acc[3] = fmaf(tp[3], wp[3], acc[3]);
            }
        }
        float* o = st2 + tl * 36 + e0;
        o[0] = gelu_f(acc[0]); o[1] = gelu_f(acc[1]);
        o[2] = gelu_f(acc[2]); o[3] = gelu_f(acc[3]);
    }
    __syncthreads();

    // Phase 3: MLP3 (32->8) + residual, 32 tokens x 8 thr
    {
        int c = sub;
        float a = sb3[c] + sx2[tl * 8 + c];
        const float* t2p = st2 + tl * 36;
#pragma unroll
        for (int q4 = 0; q4 < 8; q4++) {
            float4 tv = *(const float4*)(t2p + q4 * 4);
            int e = q4 * 4;
            a = fmaf(tv.x, sW3[(e + 0) * 8 + c], a);
            a = fmaf(tv.y, sW3[(e + 1) * 8 + c], a);
            a = fmaf(tv.z, sW3[(e + 2) * 8 + c], a);
            a = fmaf(tv.w, sW3[(e + 3) * 8 + c], a);
        }
        int p = (b << 12) | ((ti * 4 + li) << 6) | (tj * 8 + lj);
        out[p * 8 + c] = a;
    }
}

extern "C" void kernel_launch(void* const* d_in, const int* in_sizes, int n_in,
                              void* d_out, int out_size) {
    const float* x      = (const float*)d_in[0];
    const float* conv_W = (const float*)d_in[1];
    const float* conv_b = (const float*)d_in[2];
    const float* Wq     = (const float*)d_in[3];
    const float* Wk     = (const float*)d_in[4];
    const float* Wv     = (const float*)d_in[5];
    const float* pos    = (const float*)d_in[6];
    const float* Wo     = (const float*)d_in[7];
    const float* m1W    = (const float*)d_in[8];
    const float* m1b    = (const float*)d_in[9];
    const float* m2W    = (const float*)d_in[10];
    const float* m2b    = (const float*)d_in[11];
    const float* m3W    = (const float*)d_in[12];
    const float* m3b    = (const float*)d_in[13];
    float* out = (float*)d_out;

    const int ATTN_SMEM = 49152;   // 16 KB K-half + 32 KB pos quad table
    cudaFuncSetAttribute(k_attn, cudaFuncAttributeMaxDynamicSharedMemorySize, ATTN_SMEM);

    k_conv_qkv<<<256, 256>>>(x, conv_W, conv_b, Wq, Wk, Wv);
    dim3 ag(128, 4);
    k_attn<<<ag, 256, ATTN_SMEM>>>(pos);
    k_tail<<<256, 256>>>(pos, Wo, m1W, m1b, m2W, m2b, m3W, m3b, out);
}

// round 13
// speedup vs baseline: 1.2733x; 1.1054x over previous
#include <cuda_runtime.h>
#include <cuda_fp16.h>
#include <math.h>

// Problem constants: B=2, M=N=64, H=2, C=8, D=4
#define TOK  4096
#define TOT  8192

#define SCALE_LOG2E 0.72134752044448170f   // 0.5 * log2(e)

// Scratch (allocation-free: __device__ globals)
__device__ float g_x1[65536];
__device__ float g_q[65536];       // [bh][t][d], pre-scaled by 0.5*log2e
__device__ float g_k[65536];
__device__ float g_v[65536];
__device__ float g_l2[32768];      // [kh][bh][t] partial softmax denominators
__device__ uint2 g_k2[16384];      // [bh][t]: key as 2 half2
__device__ uint4 g_qt[8192];       // [h][rd][c]: pos quad-table entries (4 half2, prescaled)

__device__ __forceinline__ float gelu_f(float x) {
    float z2 = 1.5957691216057308f * fmaf(0.044715f, x * x * x, x);  // 2z
    return __fdividef(x, 1.0f + __expf(-z2));
}
__device__ __forceinline__ float ex2(float x) {
    float r; asm("ex2.approx.ftz.f32 %0, %1;" : "=f"(r) : "f"(x)); return r;
}
__device__ __forceinline__ __half2 h2ex2(__half2 x) {
    __half2 r;
    asm("ex2.approx.f16x2 %0, %1;"
        : "=r"(*reinterpret_cast<unsigned*>(&r))
        : "r"(*reinterpret_cast<const unsigned*>(&x)));
    return r;
}
__device__ __forceinline__ unsigned h2u(__half2 h) {
    return *reinterpret_cast<unsigned*>(&h);
}

// ---------------- Stage 1: gelu + circular conv (8->8) + residual + QKV ----------------
// 4x8 token tile, 8 threads/token. Side jobs: g_qt table (blocks 0-31), g_k2 pack.
__global__ void __launch_bounds__(256) k_conv_qkv(
        const float* __restrict__ x, const float* __restrict__ W,
        const float* __restrict__ bias, const float* __restrict__ Wq,
        const float* __restrict__ Wk, const float* __restrict__ Wv,
        const float* __restrict__ pos) {
    __shared__ float sW[576];
    __shared__ float sb[8];
    __shared__ float sQKV[192];
    __shared__ float sX[60 * 8];   // 6x10 halo gelu tile
    int tid = threadIdx.x;
    for (int i = tid; i < 576; i += 256) sW[i] = W[i];
    if (tid < 8) sb[tid] = bias[tid];
    if (tid < 64) {
        sQKV[tid]       = Wq[tid];
        sQKV[64 + tid]  = Wk[tid];
        sQKV[128 + tid] = Wv[tid];
    }

    // side job: pos quad table (one entry per thread, first 32 blocks)
    int gid = blockIdx.x * 256 + tid;
    if (gid < 8192) {
        int hh = gid >> 12, rd = (gid >> 6) & 63, c = gid & 63;
        const float* pr = pos + hh * 4096 + (rd << 6);
        __half2 p0 = __floats2half2_rn(pr[c] * SCALE_LOG2E,            pr[(c + 1) & 63] * SCALE_LOG2E);
        __half2 p1 = __floats2half2_rn(pr[(c + 2) & 63] * SCALE_LOG2E, pr[(c + 3) & 63] * SCALE_LOG2E);
        __half2 p2 = __floats2half2_rn(pr[(c + 4) & 63] * SCALE_LOG2E, pr[(c + 5) & 63] * SCALE_LOG2E);
        __half2 p3 = __floats2half2_rn(pr[(c + 6) & 63] * SCALE_LOG2E, pr[(c + 7) & 63] * SCALE_LOG2E);
        uint4 ent; ent.x = h2u(p0); ent.y = h2u(p1); ent.z = h2u(p2); ent.w = h2u(p3);
        g_qt[gid] = ent;
    }

    int b = blockIdx.x >> 7;
    int tile = blockIdx.x & 127;
    int ti = tile >> 3, tj = tile & 7;
    // halo gelu: both loads issued before any math
    {
        int u0 = tid, u1 = tid + 256;
        int cell0 = u0 >> 3, ch0 = u0 & 7;
        int pi0 = cell0 / 10, pj0 = cell0 - pi0 * 10;
        int row0 = (ti * 4 + pi0 - 1) & 63, col0 = (tj * 8 + pj0 - 1) & 63;
        float xv0 = x[((((b << 12) | (row0 << 6)) | col0) << 3) + ch0];
        float xv1 = 0.f;
        if (u1 < 480) {
            int cell1 = u1 >> 3, ch1 = u1 & 7;
            int pi1 = cell1 / 10, pj1 = cell1 - pi1 * 10;
            int row1 = (ti * 4 + pi1 - 1) & 63, col1 = (tj * 8 + pj1 - 1) & 63;
            xv1 = x[((((b << 12) | (row1 << 6)) | col1) << 3) + ch1];
        }
        sX[u0] = gelu_f(xv0);
        if (u1 < 480) sX[u1] = gelu_f(xv1);
    }
    __syncthreads();

    int tl = tid >> 3, cin = tid & 7;
    int li = tl >> 3, lj = tl & 7;
    int p = (b << 12) | ((ti * 4 + li) << 6) | (tj * 8 + lj);
    float acc[8];
#pragma unroll
    for (int c = 0; c < 8; c++) acc[c] = 0.f;
#pragma unroll
    for (int di = 0; di < 3; di++) {
#pragma unroll
        for (int dj = 0; dj < 3; dj++) {
            float xv = sX[((li + di) * 10 + (lj + dj)) * 8 + cin];
            const float* wp = sW + (di * 3 + dj) * 64 + cin * 8;
#pragma unroll
            for (int c = 0; c < 8; c++) acc[c] = fmaf(xv, wp[c], acc[c]);
        }
    }
    if (cin == 0) {
        float4 xa = *(const float4*)(x + p * 8);
        float4 xb = *(const float4*)(x + p * 8 + 4);
        acc[0] += sb[0] + xa.x; acc[1] += sb[1] + xa.y;
        acc[2] += sb[2] + xa.z; acc[3] += sb[3] + xa.w;
        acc[4] += sb[4] + xb.x; acc[5] += sb[5] + xb.y;
        acc[6] += sb[6] + xb.z; acc[7] += sb[7] + xb.w;
    }
#pragma unroll
    for (int c = 0; c < 8; c++) acc[c] += __shfl_xor_sync(0xffffffffu, acc[c], 1);
#pragma unroll
    for (int c = 0; c < 8; c++) acc[c] += __shfl_xor_sync(0xffffffffu, acc[c], 2);
#pragma unroll
    for (int c = 0; c < 8; c++) acc[c] += __shfl_xor_sync(0xffffffffu, acc[c], 4);

    int t = p & 4095;
    int e = cin;
    g_x1[p * 8 + e] = acc[e];
    float y[8];
#pragma unroll
    for (int c = 0; c < 8; c++) y[c] = acc[c] * 0.70710678118654752f;
    float qe = 0.f, ke = 0.f, ve = 0.f;
#pragma unroll
    for (int c = 0; c < 8; c++) {
        qe = fmaf(y[c], sQKV[c * 8 + e], qe);
        ke = fmaf(y[c], sQKV[64 + c * 8 + e], ke);
        ve = fmaf(y[c], sQKV[128 + c * 8 + e], ve);
    }
    int h = e >> 2, d = e & 3;
    int bh = (b << 1) | h;
    int idx = ((bh * TOK + t) << 2) + d;
    g_q[idx] = qe * SCALE_LOG2E;
    g_k[idx] = ke;
    g_v[idx] = ve;
    // pack key halves: even-d threads write (ke_d, ke_{d+1}) as half2
    float ke_n = __shfl_down_sync(0xffffffffu, ke, 1);
    if ((e & 1) == 0) {
        unsigned* kdst = (unsigned*)&g_k2[bh * TOK + t];
        kdst[d >> 1] = h2u(__floats2half2_rn(ke, ke_n));
    }
}

// ---------------- Stage 2: attention partial denominators ----------------
// Key-split: grid (128, 4): blockIdx.x = mi*2 + kh. Prologue is pure uint4 copies
// from g_k2 / g_qt. Main loop unchanged from R12.
__global__ void __launch_bounds__(256) k_attn() {
    extern __shared__ float smem[];
    __half2* sK2 = (__half2*)smem;          // 2048 keys x 2 half2 (16 KB)
    uint4*   sQT = (uint4*)(smem + 4096);   // 32 rows x 64 entries (32 KB)
    int mi = blockIdx.x >> 1, kh = blockIdx.x & 1;
    int bh = blockIdx.y, h = bh & 1;
    int tid = threadIdx.x;

    const uint4* gK4 = (const uint4*)(g_k2 + bh * TOK + kh * 2048);
    uint4* sK4 = (uint4*)sK2;
#pragma unroll
    for (int r = 0; r < 4; r++) sK4[tid + r * 256] = gK4[tid + r * 256];
    int rowbase = mi - kh * 32;
    const uint4* gQT = g_qt + (h << 12);
#pragma unroll
    for (int r = 0; r < 8; r++) {
        int u = tid + r * 256;
        int rb = u >> 6, c = u & 63;
        sQT[u] = gQT[(((rowbase - rb) & 63) << 6) | c];
    }
    __syncthreads();

    int warp = tid >> 5, lane = tid & 31;
    int nbase = warp * 8;
    int qbase = (mi << 6) | nbase;

    __half2 qh[4][4];
#pragma unroll
    for (int pr2 = 0; pr2 < 4; pr2++) {
        float4 qa = *(const float4*)(g_q + (bh * TOK + qbase + 2 * pr2) * 4);
        float4 qb = *(const float4*)(g_q + (bh * TOK + qbase + 2 * pr2 + 1) * 4);
        qh[pr2][0] = __floats2half2_rn(qa.x, qb.x);
        qh[pr2][1] = __floats2half2_rn(qa.y, qb.y);
        qh[pr2][2] = __floats2half2_rn(qa.z, qb.z);
        qh[pr2][3] = __floats2half2_rn(qa.w, qb.w);
    }

    int c0 = (nbase - lane) & 63;
    const uint4* qtA = sQT + c0;
    const uint4* qtB = sQT + (c0 ^ 32);
    const uint2* kp = (const uint2*)sK2 + lane;

    float l[8];
#pragma unroll
    for (int u = 0; u < 8; u++) l[u] = 0.f;

#pragma unroll 1
    for (int blk = 0; blk < 4; blk++) {
        __half2 accA[4], accB[4];
#pragma unroll
        for (int pr2 = 0; pr2 < 4; pr2++) {
            accA[pr2] = __floats2half2_rn(0.f, 0.f);
            accB[pr2] = __floats2half2_rn(0.f, 0.f);
        }
#pragma unroll
        for (int it = 0; it < 8; it++) {
            uint2 ka = kp[it * 64];
            uint2 kb = kp[it * 64 + 32];
            uint4 pa = qtA[it * 64];
            uint4 pb = qtB[it * 64];
            __half2 ka01 = *reinterpret_cast<__half2*>(&ka.x);
            __half2 ka23 = *reinterpret_cast<__half2*>(&ka.y);
            __half2 kb01 = *reinterpret_cast<__half2*>(&kb.x);
            __half2 kb23 = *reinterpret_cast<__half2*>(&kb.y);
            __half2 a0 = __low2half2(ka01), a1 = __high2half2(ka01);
            __half2 a2 = __low2half2(ka23), a3 = __high2half2(ka23);
            __half2 b0 = __low2half2(kb01), b1 = __high2half2(kb01);
            __half2 b2 = __low2half2(kb23), b3 = __high2half2(kb23);
            const unsigned* pav = &pa.x;
            const unsigned* pbv = &pb.x;
#pragma unroll
            for (int pr2 = 0; pr2 < 4; pr2++) {
                __half2 s = *reinterpret_cast<const __half2*>(&pav[pr2]);
                s = __hfma2(qh[pr2][0], a0, s);
                s = __hfma2(qh[pr2][1], a1, s);
                s = __hfma2(qh[pr2][2], a2, s);
                s = __hfma2(qh[pr2][3], a3, s);
                accA[pr2] = __hadd2(accA[pr2], h2ex2(s));
                __half2 t2 = *reinterpret_cast<const __half2*>(&pbv[pr2]);
                t2 = __hfma2(qh[pr2][0], b0, t2);
                t2 = __hfma2(qh[pr2][1], b1, t2);
                t2 = __hfma2(qh[pr2][2], b2, t2);
                t2 = __hfma2(qh[pr2][3], b3, t2);
                accB[pr2] = __hadd2(accB[pr2], h2ex2(t2));
            }
        }
        kp += 512; qtA += 512; qtB += 512;
#pragma unroll
        for (int pr2 = 0; pr2 < 4; pr2++) {
            l[2 * pr2]     += __low2float(accA[pr2])  + __low2float(accB[pr2]);
            l[2 * pr2 + 1] += __high2float(accA[pr2]) + __high2float(accB[pr2]);
        }
    }

#pragma unroll
    for (int u = 0; u < 8; u++) {
#pragma unroll
        for (int off = 16; off > 0; off >>= 1)
            l[u] += __shfl_xor_sync(0xffffffffu, l[u], off);
    }
    if (lane == 0) {
        float* dst = g_l2 + ((kh * 4 + bh) << 12) + qbase;
        dst[0] = l[0]; dst[1] = l[1]; dst[2] = l[2]; dst[3] = l[3];
        dst[4] = l[4]; dst[5] = l[5]; dst[6] = l[6]; dst[7] = l[7];
    }
}

// ---------------- Stage 3: fused tail (256 thr) ----------------
// Attention normalize (diagonal) + Wo proj + residual -> sx2; MLP1 + gelu -> st1 (halo);
// dw conv + gelu -> st2; MLP3 + residual -> out. 4x8 interior tile, halo 6x10. grid=256.
__global__ void __launch_bounds__(256) k_tail(
        const float* __restrict__ pos,
        const float* __restrict__ Wo,
        const float* __restrict__ W1, const float* __restrict__ b1,
        const float* __restrict__ W2, const float* __restrict__ b2,
        const float* __restrict__ W3, const float* __restrict__ b3,
        float* __restrict__ out) {
    __shared__ float sWo[64];
    __shared__ float sW1[256];
    __shared__ float sb1[32];
    __shared__ float sW2[288];
    __shared__ float sb2[32];
    __shared__ float sW3[256];
    __shared__ float sb3[8];
    __shared__ float st1[60 * 36];
    __shared__ float st2[32 * 36];
    __shared__ float sx2[32 * 8];
    int tid = threadIdx.x;
    if (tid < 64) sWo[tid] = Wo[tid];
    sW1[tid] = W1[tid];
    if (tid < 32) sb1[tid] = b1[tid];
    sW2[tid] = W2[tid];
    if (tid < 32) sW2[256 + tid] = W2[256 + tid];
    if (tid < 32) sb2[tid] = b2[tid];
    sW3[tid] = W3[tid];
    if (tid < 8) sb3[tid] = b3[tid];
    __syncthreads();

    int b = blockIdx.x >> 7;
    int tile = blockIdx.x & 127;
    int ti = tile >> 3, tj = tile & 7;

    // Phase 1: attention normalize + Wo proj + residual + MLP1, 60 halo tokens x 4 thr
    if (tid < 240) {
        int token = tid >> 2, quarter = tid & 3;
        int pi = token / 10, pj = token - pi * 10;
        int row = (ti * 4 + pi - 1) & 63;
        int col = (tj * 8 + pj - 1) & 63;
        int p = (b << 12) | (row << 6) | col;
        int t = p & 4095;
        float vec[8];
#pragma unroll
        for (int hh = 0; hh < 2; hh++) {
            int bh = (b << 1) | hh;
            int base = (bh * TOK + t) << 2;
            float4 q = *(const float4*)(g_q + base);
            float4 k = *(const float4*)(g_k + base);
            float4 v = *(const float4*)(g_v + base);
            float lsum = g_l2[(bh << 12) + t] + g_l2[16384 + (bh << 12) + t];
            float s = pos[hh * 4096] * SCALE_LOG2E;   // diagonal bias R[h,0,0]
            s = fmaf(q.x, k.x, s);
            s = fmaf(q.y, k.y, s);
            s = fmaf(q.z, k.z, s);
            s = fmaf(q.w, k.w, s);
            float w = __fdividef(ex2(s), lsum);
            vec[hh * 4 + 0] = w * v.x; vec[hh * 4 + 1] = w * v.y;
            vec[hh * 4 + 2] = w * v.z; vec[hh * 4 + 3] = w * v.w;
        }
        float acc[8];
        float4 x1a = *(const float4*)(g_x1 + p * 8);
        float4 x1b = *(const float4*)(g_x1 + p * 8 + 4);
        acc[0] = x1a.x; acc[1] = x1a.y; acc[2] = x1a.z; acc[3] = x1a.w;
        acc[4] = x1b.x; acc[5] = x1b.y; acc[6] = x1b.z; acc[7] = x1b.w;
#pragma unroll
        for (int e = 0; e < 8; e++)
#pragma unroll
            for (int c = 0; c < 8; c++) acc[c] = fmaf(vec[e], sWo[e * 8 + c], acc[c]);
        if (quarter == 0 && pi >= 1 && pi <= 4 && pj >= 1 && pj <= 8) {
            int lt = (pi - 1) * 8 + (pj - 1);
            *(float4*)(sx2 + lt * 8)     = make_float4(acc[0], acc[1], acc[2], acc[3]);
            *(float4*)(sx2 + lt * 8 + 4) = make_float4(acc[4], acc[5], acc[6], acc[7]);
        }
        float y[8];
#pragma unroll
        for (int c = 0; c < 8; c++) y[c] = acc[c] * 0.57735026918962576f;
        int e0 = quarter * 8;
        float* dst = st1 + token * 36 + e0;
#pragma unroll
        for (int ee = 0; ee < 8; ee++) {
            int e = e0 + ee;
            float v = sb1[e];
#pragma unroll
            for (int c = 0; c < 8; c++) v = fmaf(y[c], sW1[c * 32 + e], v);
            dst[ee] = gelu_f(v);
        }
    }
    __syncthreads();

    // Phase 2: depthwise 3x3 conv + gelu, 32 tokens x 8 thr (4 ch each)
    int tl = tid >> 3, sub = tid & 7, e0 = sub * 4;
    int li = tl >> 3, lj = tl & 7;
    {
        float acc[4];
#pragma unroll
        for (int ee = 0; ee < 4; ee++) acc[ee] = sb2[e0 + ee];
#pragma unroll
        for (int di = 0; di < 3; di++) {
#pragma unroll
            for (int dj = 0; dj < 3; dj++) {
                const float* tp = st1 + ((li + di) * 10 + (lj + dj)) * 36 + e0;
                const float* wp = sW2 + (di * 3 + dj) * 32 + e0;
                acc[0] = fmaf(tp[0], wp[0], acc[0]);
                acc[1] = fmaf(tp[1], wp[1], acc[1]);
                acc[2] = fmaf(tp[2], wp[2], acc[2]);
                acc[3] = fmaf(tp[3], wp[3], acc[3]);
            }
        }
        float* o = st2 + tl * 36 + e0;
        o[0] = gelu_f(acc[0]); o[1] = gelu_f(acc[1]);
        o[2] = gelu_f(acc[2]); o[3] = gelu_f(acc[3]);
    }
    __syncthreads();

    // Phase 3: MLP3 (32->8) + residual, 32 tokens x 8 thr
    {
        int c = sub;
        float a = sb3[c] + sx2[tl * 8 + c];
        const float* t2p = st2 + tl * 36;
#pragma unroll
        for (int q4 = 0; q4 < 8; q4++) {
            float4 tv = *(const float4*)(t2p + q4 * 4);
            int e = q4 * 4;
            a = fmaf(tv.x, sW3[(e + 0) * 8 + c], a);
            a = fmaf(tv.y, sW3[(e + 1) * 8 + c], a);
            a = fmaf(tv.z, sW3[(e + 2) * 8 + c], a);
            a = fmaf(tv.w, sW3[(e + 3) * 8 + c], a);
        }
        int p = (b << 12) | ((ti * 4 + li) << 6) | (tj * 8 + lj);
        out[p * 8 + c] = a;
    }
}

extern "C" void kernel_launch(void* const* d_in, const int* in_sizes, int n_in,
                              void* d_out, int out_size) {
    const float* x      = (const float*)d_in[0];
    const float* conv_W = (const float*)d_in[1];
    const float* conv_b = (const float*)d_in[2];
    const float* Wq     = (const float*)d_in[3];
    const float* Wk     = (const float*)d_in[4];
    const float* Wv     = (const float*)d_in[5];
    const float* pos    = (const float*)d_in[6];
    const float* Wo     = (const float*)d_in[7];
    const float* m1W    = (const float*)d_in[8];
    const float* m1b    = (const float*)d_in[9];
    const float* m2W    = (const float*)d_in[10];
    const float* m2b    = (const float*)d_in[11];
    const float* m3W    = (const float*)d_in[12];
    const float* m3b    = (const float*)d_in[13];
    float* out = (float*)d_out;

    const int ATTN_SMEM = 49152;   // 16 KB K-half + 32 KB pos quad table
    cudaFuncSetAttribute(k_attn, cudaFuncAttributeMaxDynamicSharedMemorySize, ATTN_SMEM);

    k_conv_qkv<<<256, 256>>>(x, conv_W, conv_b, Wq, Wk, Wv, pos);
    dim3 ag(128, 4);
    k_attn<<<ag, 256, ATTN_SMEM>>>();
    k_tail<<<256, 256>>>(pos, Wo, m1W, m1b, m2W, m2b, m3W, m3b, out);
}

// round 14
// speedup vs baseline: 1.3551x; 1.0643x over previous
#include <cuda_runtime.h>
#include <cuda_fp16.h>
#include <math.h>

// Problem constants: B=2, M=N=64, H=2, C=8, D=4
#define TOK  4096
#define TOT  8192

#define SCALE_LOG2E 0.72134752044448170f   // 0.5 * log2(e)

// Scratch (allocation-free: __device__ globals)
__device__ float g_x1[65536];
__device__ float g_q[65536];       // [bh][t][d], pre-scaled by 0.5*log2e
__device__ float g_k[65536];
__device__ float g_v[65536];
__device__ float g_l2[32768];      // [kh][bh][t] partial softmax denominators
__device__ uint2 g_k2[16384];      // [bh][t]: key as 2 half2
__device__ uint4 g_qt[8192];       // [h][rd][c]: pos quad-table entries (4 half2, prescaled)

__device__ __forceinline__ float gelu_f(float x) {
    float z2 = 1.5957691216057308f * fmaf(0.044715f, x * x * x, x);  // 2z
    return __fdividef(x, 1.0f + __expf(-z2));
}
__device__ __forceinline__ float ex2(float x) {
    float r; asm("ex2.approx.ftz.f32 %0, %1;" : "=f"(r) : "f"(x)); return r;
}
__device__ __forceinline__ __half2 h2ex2(__half2 x) {
    __half2 r;
    asm("ex2.approx.f16x2 %0, %1;"
        : "=r"(*reinterpret_cast<unsigned*>(&r))
        : "r"(*reinterpret_cast<const unsigned*>(&x)));
    return r;
}
__device__ __forceinline__ unsigned h2u(__half2 h) {
    return *reinterpret_cast<unsigned*>(&h);
}

// ---------------- Stage 1: gelu + circular conv (8->8) + residual + QKV ----------------
// 4x8 token tile, 8 threads/token. Side job (spread): g_qt table, 32 entries/block.
__global__ void __launch_bounds__(256) k_conv_qkv(
        const float* __restrict__ x, const float* __restrict__ W,
        const float* __restrict__ bias, const float* __restrict__ Wq,
        const float* __restrict__ Wk, const float* __restrict__ Wv,
        const float* __restrict__ pos) {
    __shared__ float sW[576];
    __shared__ float sb[8];
    __shared__ float sQKV[192];
    __shared__ float sX[60 * 8];   // 6x10 halo gelu tile
    int tid = threadIdx.x;
    for (int i = tid; i < 576; i += 256) sW[i] = W[i];
    if (tid < 8) sb[tid] = bias[tid];
    if (tid < 64) {
        sQKV[tid]       = Wq[tid];
        sQKV[64 + tid]  = Wk[tid];
        sQKV[128 + tid] = Wv[tid];
    }

    // side job: pos quad table, spread over all blocks (32 entries each)
    if (tid < 32) {
        int gid = blockIdx.x * 32 + tid;
        int hh = gid >> 12, rd = (gid >> 6) & 63, c = gid & 63;
        const float* pr = pos + hh * 4096 + (rd << 6);
        __half2 p0 = __floats2half2_rn(pr[c] * SCALE_LOG2E,            pr[(c + 1) & 63] * SCALE_LOG2E);
        __half2 p1 = __floats2half2_rn(pr[(c + 2) & 63] * SCALE_LOG2E, pr[(c + 3) & 63] * SCALE_LOG2E);
        __half2 p2 = __floats2half2_rn(pr[(c + 4) & 63] * SCALE_LOG2E, pr[(c + 5) & 63] * SCALE_LOG2E);
        __half2 p3 = __floats2half2_rn(pr[(c + 6) & 63] * SCALE_LOG2E, pr[(c + 7) & 63] * SCALE_LOG2E);
        uint4 ent; ent.x = h2u(p0); ent.y = h2u(p1); ent.z = h2u(p2); ent.w = h2u(p3);
        g_qt[gid] = ent;
    }

    int b = blockIdx.x >> 7;
    int tile = blockIdx.x & 127;
    int ti = tile >> 3, tj = tile & 7;
    // halo gelu: both loads issued before any math
    {
        int u0 = tid, u1 = tid + 256;
        int cell0 = u0 >> 3, ch0 = u0 & 7;
        int pi0 = cell0 / 10, pj0 = cell0 - pi0 * 10;
        int row0 = (ti * 4 + pi0 - 1) & 63, col0 = (tj * 8 + pj0 - 1) & 63;
        float xv0 = x[((((b << 12) | (row0 << 6)) | col0) << 3) + ch0];
        float xv1 = 0.f;
        if (u1 < 480) {
            int cell1 = u1 >> 3, ch1 = u1 & 7;
            int pi1 = cell1 / 10, pj1 = cell1 - pi1 * 10;
            int row1 = (ti * 4 + pi1 - 1) & 63, col1 = (tj * 8 + pj1 - 1) & 63;
            xv1 = x[((((b << 12) | (row1 << 6)) | col1) << 3) + ch1];
        }
        sX[u0] = gelu_f(xv0);
        if (u1 < 480) sX[u1] = gelu_f(xv1);
    }
    __syncthreads();

    int tl = tid >> 3, cin = tid & 7;
    int li = tl >> 3, lj = tl & 7;
    int p = (b << 12) | ((ti * 4 + li) << 6) | (tj * 8 + lj);
    float acc[8];
#pragma unroll
    for (int c = 0; c < 8; c++) acc[c] = 0.f;
#pragma unroll
    for (int di = 0; di < 3; di++) {
#pragma unroll
        for (int dj = 0; dj < 3; dj++) {
            float xv = sX[((li + di) * 10 + (lj + dj)) * 8 + cin];
            const float* wp = sW + (di * 3 + dj) * 64 + cin * 8;
#pragma unroll
            for (int c = 0; c < 8; c++) acc[c] = fmaf(xv, wp[c], acc[c]);
        }
    }
    if (cin == 0) {
        float4 xa = *(const float4*)(x + p * 8);
        float4 xb = *(const float4*)(x + p * 8 + 4);
        acc[0] += sb[0] + xa.x; acc[1] += sb[1] + xa.y;
        acc[2] += sb[2] + xa.z; acc[3] += sb[3] + xa.w;
        acc[4] += sb[4] + xb.x; acc[5] += sb[5] + xb.y;
        acc[6] += sb[6] + xb.z; acc[7] += sb[7] + xb.w;
    }
#pragma unroll
    for (int c = 0; c < 8; c++) acc[c] += __shfl_xor_sync(0xffffffffu, acc[c], 1);
#pragma unroll
    for (int c = 0; c < 8; c++) acc[c] += __shfl_xor_sync(0xffffffffu, acc[c], 2);
#pragma unroll
    for (int c = 0; c < 8; c++) acc[c] += __shfl_xor_sync(0xffffffffu, acc[c], 4);

    int t = p & 4095;
    int e = cin;
    g_x1[p * 8 + e] = acc[e];
    float y[8];
#pragma unroll
    for (int c = 0; c < 8; c++) y[c] = acc[c] * 0.70710678118654752f;
    float qe = 0.f, ke = 0.f, ve = 0.f;
#pragma unroll
    for (int c = 0; c < 8; c++) {
        qe = fmaf(y[c], sQKV[c * 8 + e], qe);
        ke = fmaf(y[c], sQKV[64 + c * 8 + e], ke);
        ve = fmaf(y[c], sQKV[128 + c * 8 + e], ve);
    }
    int h = e >> 2, d = e & 3;
    int bh = (b << 1) | h;
    int idx = ((bh * TOK + t) << 2) + d;
    g_q[idx] = qe * SCALE_LOG2E;
    g_k[idx] = ke;
    g_v[idx] = ve;
    // pack key halves: even-d threads write (ke_d, ke_{d+1}) as half2
    float ke_n = __shfl_down_sync(0xffffffffu, ke, 1);
    if ((e & 1) == 0) {
        unsigned* kdst = (unsigned*)&g_k2[bh * TOK + t];
        kdst[d >> 1] = h2u(__floats2half2_rn(ke, ke_n));
    }
    cudaTriggerProgrammaticLaunchCompletion();
}

// ---------------- Stage 2: attention partial denominators ----------------
// Key-split: grid (128, 4): blockIdx.x = mi*2 + kh. PDL secondary: grid-dep sync first.
__global__ void __launch_bounds__(256) k_attn() {
    extern __shared__ float smem[];
    __half2* sK2 = (__half2*)smem;          // 2048 keys x 2 half2 (16 KB)
    uint4*   sQT = (uint4*)(smem + 4096);   // 32 rows x 64 entries (32 KB)
    int mi = blockIdx.x >> 1, kh = blockIdx.x & 1;
    int bh = blockIdx.y, h = bh & 1;
    int tid = threadIdx.x;

    cudaGridDependencySynchronize();   // wait for conv outputs

    const uint4* gK4 = (const uint4*)(g_k2 + bh * TOK + kh * 2048);
    uint4* sK4 = (uint4*)sK2;
#pragma unroll
    for (int r = 0; r < 4; r++) sK4[tid + r * 256] = gK4[tid + r * 256];
    int rowbase = mi - kh * 32;
    const uint4* gQT = g_qt + (h << 12);
#pragma unroll
    for (int r = 0; r < 8; r++) {
        int u = tid + r * 256;
        int rb = u >> 6, c = u & 63;
        sQT[u] = gQT[(((rowbase - rb) & 63) << 6) | c];
    }
    __syncthreads();

    int warp = tid >> 5, lane = tid & 31;
    int nbase = warp * 8;
    int qbase = (mi << 6) | nbase;

    __half2 qh[4][4];
#pragma unroll
    for (int pr2 = 0; pr2 < 4; pr2++) {
        float4 qa = *(const float4*)(g_q + (bh * TOK + qbase + 2 * pr2) * 4);
        float4 qb = *(const float4*)(g_q + (bh * TOK + qbase + 2 * pr2 + 1) * 4);
        qh[pr2][0] = __floats2half2_rn(qa.x, qb.x);
        qh[pr2][1] = __floats2half2_rn(qa.y, qb.y);
        qh[pr2][2] = __floats2half2_rn(qa.z, qb.z);
        qh[pr2][3] = __floats2half2_rn(qa.w, qb.w);
    }

    int c0 = (nbase - lane) & 63;
    const uint4* qtA = sQT + c0;
    const uint4* qtB = sQT + (c0 ^ 32);
    const uint2* kp = (const uint2*)sK2 + lane;

    float l[8];
#pragma unroll
    for (int u = 0; u < 8; u++) l[u] = 0.f;

#pragma unroll 1
    for (int blk = 0; blk < 4; blk++) {
        __half2 accA[4], accB[4];
#pragma unroll
        for (int pr2 = 0; pr2 < 4; pr2++) {
            accA[pr2] = __floats2half2_rn(0.f, 0.f);
            accB[pr2] = __floats2half2_rn(0.f, 0.f);
        }
#pragma unroll
        for (int it = 0; it < 8; it++) {
            uint2 ka = kp[it * 64];
            uint2 kb = kp[it * 64 + 32];
            uint4 pa = qtA[it * 64];
            uint4 pb = qtB[it * 64];
            __half2 ka01 = *reinterpret_cast<__half2*>(&ka.x);
            __half2 ka23 = *reinterpret_cast<__half2*>(&ka.y);
            __half2 kb01 = *reinterpret_cast<__half2*>(&kb.x);
            __half2 kb23 = *reinterpret_cast<__half2*>(&kb.y);
            __half2 a0 = __low2half2(ka01), a1 = __high2half2(ka01);
            __half2 a2 = __low2half2(ka23), a3 = __high2half2(ka23);
            __half2 b0 = __low2half2(kb01), b1 = __high2half2(kb01);
            __half2 b2 = __low2half2(kb23), b3 = __high2half2(kb23);
            const unsigned* pav = &pa.x;
            const unsigned* pbv = &pb.x;
#pragma unroll
            for (int pr2 = 0; pr2 < 4; pr2++) {
                __half2 s = *reinterpret_cast<const __half2*>(&pav[pr2]);
                s = __hfma2(qh[pr2][0], a0, s);
                s = __hfma2(qh[pr2][1], a1, s);
                s = __hfma2(qh[pr2][2], a2, s);
                s = __hfma2(qh[pr2][3], a3, s);
                accA[pr2] = __hadd2(accA[pr2], h2ex2(s));
                __half2 t2 = *reinterpret_cast<const __half2*>(&pbv[pr2]);
                t2 = __hfma2(qh[pr2][0], b0, t2);
                t2 = __hfma2(qh[pr2][1], b1, t2);
                t2 = __hfma2(qh[pr2][2], b2, t2);
                t2 = __hfma2(qh[pr2][3], b3, t2);
                accB[pr2] = __hadd2(accB[pr2], h2ex2(t2));
            }
        }
        kp += 512; qtA += 512; qtB += 512;
#pragma unroll
        for (int pr2 = 0; pr2 < 4; pr2++) {
            l[2 * pr2]     += __low2float(accA[pr2])  + __low2float(accB[pr2]);
            l[2 * pr2 + 1] += __high2float(accA[pr2]) + __high2float(accB[pr2]);
        }
    }

#pragma unroll
    for (int u = 0; u < 8; u++) {
#pragma unroll
        for (int off = 16; off > 0; off >>= 1)
            l[u] += __shfl_xor_sync(0xffffffffu, l[u], off);
    }
    if (lane == 0) {
        float* dst = g_l2 + ((kh * 4 + bh) << 12) + qbase;
        dst[0] = l[0]; dst[1] = l[1]; dst[2] = l[2]; dst[3] = l[3];
        dst[4] = l[4]; dst[5] = l[5]; dst[6] = l[6]; dst[7] = l[7];
    }
    cudaTriggerProgrammaticLaunchCompletion();
}

// ---------------- Stage 3: fused tail (256 thr) ----------------
// PDL secondary: weight smem loads PRE-sync (inputs only), then grid-dep sync.
__global__ void __launch_bounds__(256) k_tail(
        const float* __restrict__ pos,
        const float* __restrict__ Wo,
        const float* __restrict__ W1, const float* __restrict__ b1,
        const float* __restrict__ W2, const float* __restrict__ b2,
        const float* __restrict__ W3, const float* __restrict__ b3,
        float* __restrict__ out) {
    __shared__ float sWo[64];
    __shared__ float sW1[256];
    __shared__ float sb1[32];
    __shared__ float sW2[288];
    __shared__ float sb2[32];
    __shared__ float sW3[256];
    __shared__ float sb3[8];
    __shared__ float st1[60 * 36];
    __shared__ float st2[32 * 36];
    __shared__ float sx2[32 * 8];
    int tid = threadIdx.x;
    // pre-sync: weights are kernel inputs, independent of attention
    if (tid < 64) sWo[tid] = Wo[tid];
    sW1[tid] = W1[tid];
    if (tid < 32) sb1[tid] = b1[tid];
    sW2[tid] = W2[tid];
    if (tid < 32) sW2[256 + tid] = W2[256 + tid];
    if (tid < 32) sb2[tid] = b2[tid];
    sW3[tid] = W3[tid];
    if (tid < 8) sb3[tid] = b3[tid];

    cudaGridDependencySynchronize();   // wait for attention partials
    __syncthreads();

    int b = blockIdx.x >> 7;
    int tile = blockIdx.x & 127;
    int ti = tile >> 3, tj = tile & 7;

    // Phase 1: attention normalize + Wo proj + residual + MLP1, 60 halo tokens x 4 thr
    if (tid < 240) {
        int token = tid >> 2, quarter = tid & 3;
        int pi = token / 10, pj = token - pi * 10;
        int row = (ti * 4 + pi - 1) & 63;
        int col = (tj * 8 + pj - 1) & 63;
        int p = (b << 12) | (row << 6) | col;
        int t = p & 4095;
        float vec[8];
#pragma unroll
        for (int hh = 0; hh < 2; hh++) {
            int bh = (b << 1) | hh;
            int base = (bh * TOK + t) << 2;
            float4 q = *(const float4*)(g_q + base);
            float4 k = *(const float4*)(g_k + base);
            float4 v = *(const float4*)(g_v + base);
            float lsum = g_l2[(bh << 12) + t] + g_l2[16384 + (bh << 12) + t];
            float s = pos[hh * 4096] * SCALE_LOG2E;   // diagonal bias R[h,0,0]
            s = fmaf(q.x, k.x, s);
            s = fmaf(q.y, k.y, s);
            s = fmaf(q.z, k.z, s);
            s = fmaf(q.w, k.w, s);
            float w = __fdividef(ex2(s), lsum);
            vec[hh * 4 + 0] = w * v.x; vec[hh * 4 + 1] = w * v.y;
            vec[hh * 4 + 2] = w * v.z; vec[hh * 4 + 3] = w * v.w;
        }
        float acc[8];
        float4 x1a = *(const float4*)(g_x1 + p * 8);
        float4 x1b = *(const float4*)(g_x1 + p * 8 + 4);
        acc[0] = x1a.x; acc[1] = x1a.y; acc[2] = x1a.z; acc[3] = x1a.w;
        acc[4] = x1b.x; acc[5] = x1b.y; acc[6] = x1b.z; acc[7] = x1b.w;
#pragma unroll
        for (int e = 0; e < 8; e++)
#pragma unroll
            for (int c = 0; c < 8; c++) acc[c] = fmaf(vec[e], sWo[e * 8 + c], acc[c]);
        if (quarter == 0 && pi >= 1 && pi <= 4 && pj >= 1 && pj <= 8) {
            int lt = (pi - 1) * 8 + (pj - 1);
            *(float4*)(sx2 + lt * 8)     = make_float4(acc[0], acc[1], acc[2], acc[3]);
            *(float4*)(sx2 + lt * 8 + 4) = make_float4(acc[4], acc[5], acc[6], acc[7]);
        }
        float y[8];
#pragma unroll
        for (int c = 0; c < 8; c++) y[c] = acc[c] * 0.57735026918962576f;
        int e0 = quarter * 8;
        float* dst = st1 + token * 36 + e0;
#pragma unroll
        for (int ee = 0; ee < 8; ee++) {
            int e = e0 + ee;
            float v = sb1[e];
#pragma unroll
            for (int c = 0; c < 8; c++) v = fmaf(y[c], sW1[c * 32 + e], v);
            dst[ee] = gelu_f(v);
        }
    }
    __syncthreads();

    // Phase 2: depthwise 3x3 conv + gelu, 32 tokens x 8 thr (4 ch each)
    int tl = tid >> 3, sub = tid & 7, e0 = sub * 4;
    int li = tl >> 3, lj = tl & 7;
    {
        float acc[4];
#pragma unroll
        for (int ee = 0; ee < 4; ee++) acc[ee] = sb2[e0 + ee];
#pragma unroll
        for (int di = 0; di < 3; di++) {
#pragma unroll
            for (int dj = 0; dj < 3; dj++) {
                const float* tp = st1 + ((li + di) * 10 + (lj + dj)) * 36 + e0;
                const float* wp = sW2 + (di * 3 + dj) * 32 + e0;
                acc[0] = fmaf(tp[0], wp[0], acc[0]);
                acc[1] = fmaf(tp[1], wp[1], acc[1]);
                acc[2] = fmaf(tp[2], wp[2], acc[2]);
                acc[3] = fmaf(tp[3], wp[3], acc[3]);
            }
        }
        float* o = st2 + tl * 36 + e0;
        o[0] = gelu_f(acc[0]); o[1] = gelu_f(acc[1]);
        o[2] = gelu_f(acc[2]); o[3] = gelu_f(acc[3]);
    }
    __syncthreads();

    // Phase 3: MLP3 (32->8) + residual, 32 tokens x 8 thr
    {
        int c = sub;
        float a = sb3[c] + sx2[tl * 8 + c];
        const float* t2p = st2 + tl * 36;
#pragma unroll
        for (int q4 = 0; q4 < 8; q4++) {
            float4 tv = *(const float4*)(t2p + q4 * 4);
            int e = q4 * 4;
            a = fmaf(tv.x, sW3[(e + 0) * 8 + c], a);
            a = fmaf(tv.y, sW3[(e + 1) * 8 + c], a);
            a = fmaf(tv.z, sW3[(e + 2) * 8 + c], a);
            a = fmaf(tv.w, sW3[(e + 3) * 8 + c], a);
        }
        int p = (b << 12) | ((ti * 4 + li) << 6) | (tj * 8 + lj);
        out[p * 8 + c] = a;
    }
}

extern "C" void kernel_launch(void* const* d_in, const int* in_sizes, int n_in,
                              void* d_out, int out_size) {
    const float* x      = (const float*)d_in[0];
    const float* conv_W = (const float*)d_in[1];
    const float* conv_b = (const float*)d_in[2];
    const float* Wq     = (const float*)d_in[3];
    const float* Wk     = (const float*)d_in[4];
    const float* Wv     = (const float*)d_in[5];
    const float* pos    = (const float*)d_in[6];
    const float* Wo     = (const float*)d_in[7];
    const float* m1W    = (const float*)d_in[8];
    const float* m1b    = (const float*)d_in[9];
    const float* m2W    = (const float*)d_in[10];
    const float* m2b    = (const float*)d_in[11];
    const float* m3W    = (const float*)d_in[12];
    const float* m3b    = (const float*)d_in[13];
    float* out = (float*)d_out;

    const int ATTN_SMEM = 49152;   // 16 KB K-half + 32 KB pos quad table
    cudaFuncSetAttribute(k_attn, cudaFuncAttributeMaxDynamicSharedMemorySize, ATTN_SMEM);

    k_conv_qkv<<<256, 256>>>(x, conv_W, conv_b, Wq, Wk, Wv, pos);

    // PDL launch: attn overlaps conv's drain
    {
        cudaLaunchConfig_t cfg = {};
        cfg.gridDim = dim3(128, 4);
        cfg.blockDim = dim3(256);
        cfg.dynamicSmemBytes = ATTN_SMEM;
        cfg.stream = 0;
        cudaLaunchAttribute attr[1];
        attr[0].id = cudaLaunchAttributeProgrammaticStreamSerialization;
        attr[0].val.programmaticStreamSerializationAllowed = 1;
        cfg.attrs = attr;
        cfg.numAttrs = 1;
        cudaLaunchKernelEx(&cfg, k_attn);
    }

    // PDL launch: tail pre-loads weights while attn drains
    {
        cudaLaunchConfig_t cfg = {};
        cfg.gridDim = dim3(256);
        cfg.blockDim = dim3(256);
        cfg.dynamicSmemBytes = 0;
        cfg.stream = 0;
        cudaLaunchAttribute attr[1];
        attr[0].id = cudaLaunchAttributeProgrammaticStreamSerialization;
        attr[0].val.programmaticStreamSerializationAllowed = 1;
        cfg.attrs = attr;
        cfg.numAttrs = 1;
        cudaLaunchKernelEx(&cfg, k_tail, pos, Wo, m1W, m1b, m2W, m2b, m3W, m3b, out);
    }
}

// round 15
// speedup vs baseline: 1.3583x; 1.0023x over previous
#include <cuda_runtime.h>
#include <cuda_fp16.h>
#include <math.h>

// Problem constants: B=2, M=N=64, H=2, C=8, D=4
#define TOK  4096
#define TOT  8192

#define SCALE_LOG2E 0.72134752044448170f   // 0.5 * log2(e)

// Scratch (allocation-free: __device__ globals)
__device__ float g_x1[65536];
__device__ float g_q[65536];       // [bh][t][d], pre-scaled by 0.5*log2e
__device__ float g_k[65536];
__device__ float g_v[65536];
__device__ float g_l2[32768];      // [kh][bh][t] partial softmax denominators
__device__ uint2 g_k2[16384];      // [bh][t]: key as 2 half2
__device__ uint4 g_qt[8192];       // [h][rd][c]: pos quad-table entries (4 half2, prescaled)

__device__ __forceinline__ float gelu_f(float x) {
    float z2 = 1.5957691216057308f * fmaf(0.044715f, x * x * x, x);  // 2z
    return __fdividef(x, 1.0f + __expf(-z2));
}
__device__ __forceinline__ float ex2(float x) {
    float r; asm("ex2.approx.ftz.f32 %0, %1;" : "=f"(r) : "f"(x)); return r;
}
__device__ __forceinline__ __half2 h2ex2(__half2 x) {
    __half2 r;
    asm("ex2.approx.f16x2 %0, %1;"
        : "=r"(*reinterpret_cast<unsigned*>(&r))
        : "r"(*reinterpret_cast<const unsigned*>(&x)));
    return r;
}
__device__ __forceinline__ unsigned h2u(__half2 h) {
    return *reinterpret_cast<unsigned*>(&h);
}

// ---------------- Stage 1: gelu + circular conv (8->8) + residual + QKV ----------------
// 4x8 token tile, 8 threads/token. Vectorized halo fill, hoisted residual load.
__global__ void __launch_bounds__(256) k_conv_qkv(
        const float* __restrict__ x, const float* __restrict__ W,
        const float* __restrict__ bias, const float* __restrict__ Wq,
        const float* __restrict__ Wk, const float* __restrict__ Wv,
        const float* __restrict__ pos) {
    __shared__ float sW[576];
    __shared__ float sb[8];
    __shared__ float sQKV[192];
    __shared__ float sX[60 * 8];   // 6x10 halo gelu tile
    int tid = threadIdx.x;

    int b = blockIdx.x >> 7;
    int tile = blockIdx.x & 127;
    int ti = tile >> 3, tj = tile & 7;

    // vectorized halo gelu: 120 threads, 1 LDG.128 + 4 gelu + 1 STS.128 each
    if (tid < 120) {
        int cell = tid >> 1, hf = tid & 1;
        int pi = cell / 10, pj = cell - pi * 10;
        int row = (ti * 4 + pi - 1) & 63;
        int col = (tj * 8 + pj - 1) & 63;
        float4 xv = *(const float4*)(x + (((((b << 12) | (row << 6)) | col) << 3) + hf * 4));
        float4 g;
        g.x = gelu_f(xv.x); g.y = gelu_f(xv.y); g.z = gelu_f(xv.z); g.w = gelu_f(xv.w);
        *(float4*)(sX + cell * 8 + hf * 4) = g;
    }

    // weight staging (overlaps halo loads)
    for (int i = tid; i < 576; i += 256) sW[i] = W[i];
    if (tid < 8) sb[tid] = bias[tid];
    if (tid < 64) {
        sQKV[tid]       = Wq[tid];
        sQKV[64 + tid]  = Wk[tid];
        sQKV[128 + tid] = Wv[tid];
    }

    // side job: pos quad table, spread over all blocks (32 entries each)
    if (tid < 32) {
        int gid = blockIdx.x * 32 + tid;
        int hh = gid >> 12, rd = (gid >> 6) & 63, c = gid & 63;
        const float* pr = pos + hh * 4096 + (rd << 6);
        __half2 p0 = __floats2half2_rn(pr[c] * SCALE_LOG2E,            pr[(c + 1) & 63] * SCALE_LOG2E);
        __half2 p1 = __floats2half2_rn(pr[(c + 2) & 63] * SCALE_LOG2E, pr[(c + 3) & 63] * SCALE_LOG2E);
        __half2 p2 = __floats2half2_rn(pr[(c + 4) & 63] * SCALE_LOG2E, pr[(c + 5) & 63] * SCALE_LOG2E);
        __half2 p3 = __floats2half2_rn(pr[(c + 6) & 63] * SCALE_LOG2E, pr[(c + 7) & 63] * SCALE_LOG2E);
        uint4 ent; ent.x = h2u(p0); ent.y = h2u(p1); ent.z = h2u(p2); ent.w = h2u(p3);
        g_qt[gid] = ent;
    }

    int tl = tid >> 3, cin = tid & 7;
    int li = tl >> 3, lj = tl & 7;
    int p = (b << 12) | ((ti * 4 + li) << 6) | (tj * 8 + lj);

    // hoisted residual load (cin==0 threads) — latency overlaps the barrier
    float4 xra, xrb;
    if (cin == 0) {
        xra = *(const float4*)(x + p * 8);
        xrb = *(const float4*)(x + p * 8 + 4);
    }
    __syncthreads();

    float acc[8];
#pragma unroll
    for (int c = 0; c < 8; c++) acc[c] = 0.f;
#pragma unroll
    for (int di = 0; di < 3; di++) {
#pragma unroll
        for (int dj = 0; dj < 3; dj++) {
            float xv = sX[((li + di) * 10 + (lj + dj)) * 8 + cin];
            const float* wp = sW + (di * 3 + dj) * 64 + cin * 8;
#pragma unroll
            for (int c = 0; c < 8; c++) acc[c] = fmaf(xv, wp[c], acc[c]);
        }
    }
    if (cin == 0) {
        acc[0] += sb[0] + xra.x; acc[1] += sb[1] + xra.y;
        acc[2] += sb[2] + xra.z; acc[3] += sb[3] + xra.w;
        acc[4] += sb[4] + xrb.x; acc[5] += sb[5] + xrb.y;
        acc[6] += sb[6] + xrb.z; acc[7] += sb[7] + xrb.w;
    }
#pragma unroll
    for (int c = 0; c < 8; c++) acc[c] += __shfl_xor_sync(0xffffffffu, acc[c], 1);
#pragma unroll
    for (int c = 0; c < 8; c++) acc[c] += __shfl_xor_sync(0xffffffffu, acc[c], 2);
#pragma unroll
    for (int c = 0; c < 8; c++) acc[c] += __shfl_xor_sync(0xffffffffu, acc[c], 4);

    int t = p & 4095;
    int e = cin;
    g_x1[p * 8 + e] = acc[e];
    float y[8];
#pragma unroll
    for (int c = 0; c < 8; c++) y[c] = acc[c] * 0.70710678118654752f;
    float qe = 0.f, ke = 0.f, ve = 0.f;
#pragma unroll
    for (int c = 0; c < 8; c++) {
        qe = fmaf(y[c], sQKV[c * 8 + e], qe);
        ke = fmaf(y[c], sQKV[64 + c * 8 + e], ke);
        ve = fmaf(y[c], sQKV[128 + c * 8 + e], ve);
    }
    int h = e >> 2, d = e & 3;
    int bh = (b << 1) | h;
    int idx = ((bh * TOK + t) << 2) + d;
    g_q[idx] = qe * SCALE_LOG2E;
    g_k[idx] = ke;
    g_v[idx] = ve;
    // pack key halves: even-d threads write (ke_d, ke_{d+1}) as half2
    float ke_n = __shfl_down_sync(0xffffffffu, ke, 1);
    if ((e & 1) == 0) {
        unsigned* kdst = (unsigned*)&g_k2[bh * TOK + t];
        kdst[d >> 1] = h2u(__floats2half2_rn(ke, ke_n));
    }
    cudaTriggerProgrammaticLaunchCompletion();
}

// ---------------- Stage 2: attention partial denominators ----------------
// Key-split: grid (128, 4): blockIdx.x = mi*2 + kh. PDL secondary: grid-dep sync first.
__global__ void __launch_bounds__(256) k_attn() {
    extern __shared__ float smem[];
    __half2* sK2 = (__half2*)smem;          // 2048 keys x 2 half2 (16 KB)
    uint4*   sQT = (uint4*)(smem + 4096);   // 32 rows x 64 entries (32 KB)
    int mi = blockIdx.x >> 1, kh = blockIdx.x & 1;
    int bh = blockIdx.y, h = bh & 1;
    int tid = threadIdx.x;

    cudaGridDependencySynchronize();   // wait for conv outputs

    const uint4* gK4 = (const uint4*)(g_k2 + bh * TOK + kh * 2048);
    uint4* sK4 = (uint4*)sK2;
#pragma unroll
    for (int r = 0; r < 4; r++) sK4[tid + r * 256] = gK4[tid + r * 256];
    int rowbase = mi - kh * 32;
    const uint4* gQT = g_qt + (h << 12);
#pragma unroll
    for (int r = 0; r < 8; r++) {
        int u = tid + r * 256;
        int rb = u >> 6, c = u & 63;
        sQT[u] = gQT[(((rowbase - rb) & 63) << 6) | c];
    }
    __syncthreads();

    int warp = tid >> 5, lane = tid & 31;
    int nbase = warp * 8;
    int qbase = (mi << 6) | nbase;

    __half2 qh[4][4];
#pragma unroll
    for (int pr2 = 0; pr2 < 4; pr2++) {
        float4 qa = *(const float4*)(g_q + (bh * TOK + qbase + 2 * pr2) * 4);
        float4 qb = *(const float4*)(g_q + (bh * TOK + qbase + 2 * pr2 + 1) * 4);
        qh[pr2][0] = __floats2half2_rn(qa.x, qb.x);
        qh[pr2][1] = __floats2half2_rn(qa.y, qb.y);
        qh[pr2][2] = __floats2half2_rn(qa.z, qb.z);
        qh[pr2][3] = __floats2half2_rn(qa.w, qb.w);
    }

    int c0 = (nbase - lane) & 63;
    const uint4* qtA = sQT + c0;
    const uint4* qtB = sQT + (c0 ^ 32);
    const uint2* kp = (const uint2*)sK2 + lane;

    float l[8];
#pragma unroll
    for (int u = 0; u < 8; u++) l[u] = 0.f;

#pragma unroll 1
    for (int blk = 0; blk < 4; blk++) {
        __half2 accA[4], accB[4];
#pragma unroll
        for (int pr2 = 0; pr2 < 4; pr2++) {
            accA[pr2] = __floats2half2_rn(0.f, 0.f);
            accB[pr2] = __floats2half2_rn(0.f, 0.f);
        }
#pragma unroll
        for (int it = 0; it < 8; it++) {
            uint2 ka = kp[it * 64];
            uint2 kb = kp[it * 64 + 32];
            uint4 pa = qtA[it * 64];
            uint4 pb = qtB[it * 64];
            __half2 ka01 = *reinterpret_cast<__half2*>(&ka.x);
            __half2 ka23 = *reinterpret_cast<__half2*>(&ka.y);
            __half2 kb01 = *reinterpret_cast<__half2*>(&kb.x);
            __half2 kb23 = *reinterpret_cast<__half2*>(&kb.y);
            __half2 a0 = __low2half2(ka01), a1 = __high2half2(ka01);
            __half2 a2 = __low2half2(ka23), a3 = __high2half2(ka23);
            __half2 b0 = __low2half2(kb01), b1 = __high2half2(kb01);
            __half2 b2 = __low2half2(kb23), b3 = __high2half2(kb23);
            const unsigned* pav = &pa.x;
            const unsigned* pbv = &pb.x;
#pragma unroll
            for (int pr2 = 0; pr2 < 4; pr2++) {
                __half2 s = *reinterpret_cast<const __half2*>(&pav[pr2]);
                s = __hfma2(qh[pr2][0], a0, s);
                s = __hfma2(qh[pr2][1], a1, s);
                s = __hfma2(qh[pr2][2], a2, s);
                s = __hfma2(qh[pr2][3], a3, s);
                accA[pr2] = __hadd2(accA[pr2], h2ex2(s));
                __half2 t2 = *reinterpret_cast<const __half2*>(&pbv[pr2]);
                t2 = __hfma2(qh[pr2][0], b0, t2);
                t2 = __hfma2(qh[pr2][1], b1, t2);
                t2 = __hfma2(qh[pr2][2], b2, t2);
                t2 = __hfma2(qh[pr2][3], b3, t2);
                accB[pr2] = __hadd2(accB[pr2], h2ex2(t2));
            }
        }
        kp += 512; qtA += 512; qtB += 512;
#pragma unroll
        for (int pr2 = 0; pr2 < 4; pr2++) {
            l[2 * pr2]     += __low2float(accA[pr2])  + __low2float(accB[pr2]);
            l[2 * pr2 + 1] += __high2float(accA[pr2]) + __high2float(accB[pr2]);
        }
    }

#pragma unroll
    for (int u = 0; u < 8; u++) {
#pragma unroll
        for (int off = 16; off > 0; off >>= 1)
            l[u] += __shfl_xor_sync(0xffffffffu, l[u], off);
    }
    if (lane == 0) {
        float* dst = g_l2 + ((kh * 4 + bh) << 12) + qbase;
        dst[0] = l[0]; dst[1] = l[1]; dst[2] = l[2]; dst[3] = l[3];
        dst[4] = l[4]; dst[5] = l[5]; dst[6] = l[6]; dst[7] = l[7];
    }
    cudaTriggerProgrammaticLaunchCompletion();
}

// ---------------- Stage 3: fused tail (256 thr) ----------------
// PDL secondary: weight smem loads PRE-sync (inputs only), then grid-dep sync.
__global__ void __launch_bounds__(256) k_tail(
        const float* __restrict__ pos,
        const float* __restrict__ Wo,
        const float* __restrict__ W1, const float* __restrict__ b1,
        const float* __restrict__ W2, const float* __restrict__ b2,
        const float* __restrict__ W3, const float* __restrict__ b3,
        float* __restrict__ out) {
    __shared__ float sWo[64];
    __shared__ float sW1[256];
    __shared__ float sb1[32];
    __shared__ float sW2[288];
    __shared__ float sb2[32];
    __shared__ float sW3[256];
    __shared__ float sb3[8];
    __shared__ float st1[60 * 36];
    __shared__ float st2[32 * 36];
    __shared__ float sx2[32 * 8];
    int tid = threadIdx.x;
    // pre-sync: weights are kernel inputs, independent of attention
    if (tid < 64) sWo[tid] = Wo[tid];
    sW1[tid] = W1[tid];
    if (tid < 32) sb1[tid] = b1[tid];
    sW2[tid] = W2[tid];
    if (tid < 32) sW2[256 + tid] = W2[256 + tid];
    if (tid < 32) sb2[tid] = b2[tid];
    sW3[tid] = W3[tid];
    if (tid < 8) sb3[tid] = b3[tid];

    cudaGridDependencySynchronize();   // wait for attention partials
    __syncthreads();

    int b = blockIdx.x >> 7;
    int tile = blockIdx.x & 127;
    int ti = tile >> 3, tj = tile & 7;

    // Phase 1: attention normalize + Wo proj + residual + MLP1, 60 halo tokens x 4 thr
    if (tid < 240) {
        int token = tid >> 2, quarter = tid & 3;
        int pi = token / 10, pj = token - pi * 10;
        int row = (ti * 4 + pi - 1) & 63;
        int col = (tj * 8 + pj - 1) & 63;
        int p = (b << 12) | (row << 6) | col;
        int t = p & 4095;
        float vec[8];
#pragma unroll
        for (int hh = 0; hh < 2; hh++) {
            int bh = (b << 1) | hh;
            int base = (bh * TOK + t) << 2;
            float4 q = *(const float4*)(g_q + base);
            float4 k = *(const float4*)(g_k + base);
            float4 v = *(const float4*)(g_v + base);
            float lsum = g_l2[(bh << 12) + t] + g_l2[16384 + (bh << 12) + t];
            float s = pos[hh * 4096] * SCALE_LOG2E;   // diagonal bias R[h,0,0]
            s = fmaf(q.x, k.x, s);
            s = fmaf(q.y, k.y, s);
            s = fmaf(q.z, k.z, s);
            s = fmaf(q.w, k.w, s);
            float w = __fdividef(ex2(s), lsum);
            vec[hh * 4 + 0] = w * v.x; vec[hh * 4 + 1] = w * v.y;
            vec[hh * 4 + 2] = w * v.z; vec[hh * 4 + 3] = w * v.w;
        }
        float acc[8];
        float4 x1a = *(const float4*)(g_x1 + p * 8);
        float4 x1b = *(const float4*)(g_x1 + p * 8 + 4);
        acc[0] = x1a.x; acc[1] = x1a.y; acc[2] = x1a.z; acc[3] = x1a.w;
        acc[4] = x1b.x; acc[5] = x1b.y; acc[6] = x1b.z; acc[7] = x1b.w;
#pragma unroll
        for (int e = 0; e < 8; e++)
#pragma unroll
            for (int c = 0; c < 8; c++) acc[c] = fmaf(vec[e], sWo[e * 8 + c], acc[c]);
        if (quarter == 0 && pi >= 1 && pi <= 4 && pj >= 1 && pj <= 8) {
            int lt = (pi - 1) * 8 + (pj - 1);
            *(float4*)(sx2 + lt * 8)     = make_float4(acc[0], acc[1], acc[2], acc[3]);
            *(float4*)(sx2 + lt * 8 + 4) = make_float4(acc[4], acc[5], acc[6], acc[7]);
        }
        float y[8];
#pragma unroll
        for (int c = 0; c < 8; c++) y[c] = acc[c] * 0.57735026918962576f;
        int e0 = quarter * 8;
        float* dst = st1 + token * 36 + e0;
#pragma unroll
        for (int ee = 0; ee < 8; ee++) {
            int e = e0 + ee;
            float v = sb1[e];
#pragma unroll
            for (int c = 0; c < 8; c++) v = fmaf(y[c], sW1[c * 32 + e], v);
            dst[ee] = gelu_f(v);
        }
    }
    __syncthreads();

    // Phase 2: depthwise 3x3 conv + gelu, 32 tokens x 8 thr (4 ch each)
    int tl = tid >> 3, sub = tid & 7, e0 = sub * 4;
    int li = tl >> 3, lj = tl & 7;
    {
        float acc[4];
#pragma unroll
        for (int ee = 0; ee < 4; ee++) acc[ee] = sb2[e0 + ee];
#pragma unroll
        for (int di = 0; di < 3; di++) {
#pragma unroll
            for (int dj = 0; dj < 3; dj++) {
                const float* tp = st1 + ((li + di) * 10 + (lj + dj)) * 36 + e0;
                const float* wp = sW2 + (di * 3 + dj) * 32 + e0;
                acc[0] = fmaf(tp[0], wp[0], acc[0]);
                acc[1] = fmaf(tp[1], wp[1], acc[1]);
                acc[2] = fmaf(tp[2], wp[2], acc[2]);
                acc[3] = fmaf(tp[3], wp[3], acc[3]);
            }
        }
        float* o = st2 + tl * 36 + e0;
        o[0] = gelu_f(acc[0]); o[1] = gelu_f(acc[1]);
        o[2] = gelu_f(acc[2]); o[3] = gelu_f(acc[3]);
    }
    __syncthreads();

    // Phase 3: MLP3 (32->8) + residual, 32 tokens x 8 thr
    {
        int c = sub;
        float a = sb3[c] + sx2[tl * 8 + c];
        const float* t2p = st2 + tl * 36;
#pragma unroll
        for (int q4 = 0; q4 < 8; q4++) {
            float4 tv = *(const float4*)(t2p + q4 * 4);
            int e = q4 * 4;
            a = fmaf(tv.x, sW3[(e + 0) * 8 + c], a);
            a = fmaf(tv.y, sW3[(e + 1) * 8 + c], a);
            a = fmaf(tv.z, sW3[(e + 2) * 8 + c], a);
            a = fmaf(tv.w, sW3[(e + 3) * 8 + c], a);
        }
        int p = (b << 12) | ((ti * 4 + li) << 6) | (tj * 8 + lj);
        out[p * 8 + c] = a;
    }
}

extern "C" void kernel_launch(void* const* d_in, const int* in_sizes, int n_in,
                              void* d_out, int out_size) {
    const float* x      = (const float*)d_in[0];
    const float* conv_W = (const float*)d_in[1];
    const float* conv_b = (const float*)d_in[2];
    const float* Wq     = (const float*)d_in[3];
    const float* Wk     = (const float*)d_in[4];
    const float* Wv     = (const float*)d_in[5];
    const float* pos    = (const float*)d_in[6];
    const float* Wo     = (const float*)d_in[7];
    const float* m1W    = (const float*)d_in[8];
    const float* m1b    = (const float*)d_in[9];
    const float* m2W    = (const float*)d_in[10];
    const float* m2b    = (const float*)d_in[11];
    const float* m3W    = (const float*)d_in[12];
    const float* m3b    = (const float*)d_in[13];
    float* out = (float*)d_out;

    const int ATTN_SMEM = 49152;   // 16 KB K-half + 32 KB pos quad table
    cudaFuncSetAttribute(k_attn, cudaFuncAttributeMaxDynamicSharedMemorySize, ATTN_SMEM);

    k_conv_qkv<<<256, 256>>>(x, conv_W, conv_b, Wq, Wk, Wv, pos);

    // PDL launch: attn overlaps conv's drain
    {
        cudaLaunchConfig_t cfg = {};
        cfg.gridDim = dim3(128, 4);
        cfg.blockDim = dim3(256);
        cfg.dynamicSmemBytes = ATTN_SMEM;
        cfg.stream = 0;
        cudaLaunchAttribute attr[1];
        attr[0].id = cudaLaunchAttributeProgrammaticStreamSerialization;
        attr[0].val.programmaticStreamSerializationAllowed = 1;
        cfg.attrs = attr;
        cfg.numAttrs = 1;
        cudaLaunchKernelEx(&cfg, k_attn);
    }

    // PDL launch: tail pre-loads weights while attn drains
    {
        cudaLaunchConfig_t cfg = {};
        cfg.gridDim = dim3(256);
        cfg.blockDim = dim3(256);
        cfg.dynamicSmemBytes = 0;
        cfg.stream = 0;
        cudaLaunchAttribute attr[1];
        attr[0].id = cudaLaunchAttributeProgrammaticStreamSerialization;
        attr[0].val.programmaticStreamSerializationAllowed = 1;
        cfg.attrs = attr;
        cfg.numAttrs = 1;
        cudaLaunchKernelEx(&cfg, k_tail, pos, Wo, m1W, m1b, m2W, m2b, m3W, m3b, out);
    }
}